// round 13
// baseline (speedup 1.0000x reference)
#include <cuda_runtime.h>
#include <cuda_fp16.h>
#include <cstdint>
#include <math.h>

// Problem constants
#define D_MODEL 4096
#define TWO_D   8192
#define NB      8
#define SEQ     512
#define LAMBDA_INIT 0.8f

// ---------------------------------------------------------------------------
// Scratch (static device globals; no runtime allocation allowed)
// ---------------------------------------------------------------------------
__device__ __align__(256) __half g_xh [(size_t)4096 * 4096];
__device__ __align__(256) __half g_wqh[(size_t)TWO_D * 4096];
__device__ __align__(256) __half g_wql[(size_t)TWO_D * 4096];
__device__ __align__(256) __half g_wkh[(size_t)TWO_D * 4096];
__device__ __align__(256) __half g_wkl[(size_t)TWO_D * 4096];
__device__ __align__(256) __half g_wvh[(size_t)TWO_D * 4096];
__device__ __align__(256) __half g_wvl[(size_t)TWO_D * 4096];
__device__ __align__(256) __half g_qh [(size_t)NB * SEQ * TWO_D];
__device__ __align__(256) __half g_ql [(size_t)NB * SEQ * TWO_D];
__device__ __align__(256) __half g_kh [(size_t)NB * SEQ * TWO_D];
__device__ __align__(256) __half g_kl [(size_t)NB * SEQ * TWO_D];
__device__ __align__(256) __half g_vh [(size_t)NB * SEQ * TWO_D];
__device__ __align__(256) __half g_vl [(size_t)NB * SEQ * TWO_D];
__device__ __align__(256) __half g_vth[(size_t)NB * TWO_D * SEQ];
__device__ __align__(256) __half g_vtl[(size_t)NB * TWO_D * SEQ];
__device__ __align__(256) float  g_l1 [(size_t)NB * SEQ * SEQ];
__device__ __align__(256) float  g_l2 [(size_t)NB * SEQ * SEQ];
__device__ __align__(256) __half g_sch[(size_t)NB * SEQ * SEQ];
__device__ __align__(256) __half g_scl[(size_t)NB * SEQ * SEQ];

// ---------------------------------------------------------------------------
// PTX primitives (arch-neutral: sm_80+)
// ---------------------------------------------------------------------------
__device__ __forceinline__ uint32_t smem_u32(const void* p) {
    uint32_t a;
    asm("{ .reg .u64 t; cvta.to.shared.u64 t, %1; cvt.u32.u64 %0, t; }"
        : "=r"(a) : "l"(p));
    return a;
}

__device__ __forceinline__ void cpa16(uint32_t dst, const void* src) {
    asm volatile("cp.async.cg.shared.global [%0], [%1], 16;\n"
                 :: "r"(dst), "l"(src));
}
#define CP_COMMIT() asm volatile("cp.async.commit_group;\n" ::: "memory")
#define CP_WAIT(N)  asm volatile("cp.async.wait_group %0;\n" :: "n"(N) : "memory")

#define LDSM4(R, addr) \
    asm volatile("ldmatrix.sync.aligned.m8n8.x4.shared.b16 {%0,%1,%2,%3}, [%4];" \
        : "=r"((R)[0]), "=r"((R)[1]), "=r"((R)[2]), "=r"((R)[3]) : "r"(addr))

__device__ __forceinline__ void mma_f16(float* c, const uint32_t* a,
                                        uint32_t b0, uint32_t b1) {
    asm volatile(
        "mma.sync.aligned.m16n8k16.row.col.f32.f16.f16.f32 "
        "{%0,%1,%2,%3}, {%4,%5,%6,%7}, {%8,%9}, {%0,%1,%2,%3};"
        : "+f"(c[0]), "+f"(c[1]), "+f"(c[2]), "+f"(c[3])
        : "r"(a[0]), "r"(a[1]), "r"(a[2]), "r"(a[3]), "r"(b0), "r"(b1));
}

// Swizzled smem byte offset: tile row r (64B rows), 16B-granule g
__device__ __forceinline__ uint32_t swz(uint32_t r, uint32_t g) {
    return r * 64u + (((g ^ ((r >> 1) & 3u)) << 4));
}

__device__ __forceinline__ __half2 split_hl(float a, float b, __half2& lo) {
    __half ha = __float2half_rn(a), hb = __float2half_rn(b);
    lo = __halves2half2(__float2half_rn(a - __half2float(ha)),
                        __float2half_rn(b - __half2float(hb)));
    return __halves2half2(ha, hb);
}

// ---------------------------------------------------------------------------
// GEMM: C[128,256] = A[128,K] @ B[256,K]^T, fp16 split-precision HMMA
// THREE=false: 2 products (AhBh + AhBl), A hi-only      (projections)
// THREE=true : 3 products (+ AlBh), A hi+lo             (logits / output)
// STG stages, prefetch distance 3.  BS = barrier step (1 or 2):
//   BS=2 (needs STG>=5): wait_group(1)+barrier on even iters only.
// 512 threads, 16 warps (4/SMSP), warp tile 64x32
// EPI: 0 = fp32 + bias, 1 = fp32, 2 = f16 hi/lo + bias
// ---------------------------------------------------------------------------
#define BK      32
#define NTHREAD 512
#define DSMEM_BYTES_2P (5 * 40960 + 1024)
#define DSMEM_BYTES_3P (4 * 49152 + 1024)

template<int EPI, bool THREE, int STG, int BS>
__device__ __forceinline__ void gemm_body(
    const __half* __restrict__ Ah_, const __half* __restrict__ Al_, int lda,
    const __half* __restrict__ Bh_, const __half* __restrict__ Bl_, int ldb,
    int K,
    float* __restrict__ C, int ldc,
    __half* __restrict__ Ch, __half* __restrict__ Cl,
    const float* __restrict__ bias)
{
    constexpr uint32_t OFF_AL   = 8192;
    constexpr uint32_t OFF_BH   = THREE ? 16384 : 8192;
    constexpr uint32_t OFF_BL   = OFF_BH + 16384;
    constexpr uint32_t STAGE_BY = THREE ? 49152 : 40960;

    extern __shared__ char dsm_raw[];
    const uint32_t sb = (smem_u32(dsm_raw) + 1023u) & ~1023u;

    const int tid  = threadIdx.x;
    const int wid  = tid >> 5;
    const int lane = tid & 31;
    const int warp_m = wid & 1;       // 2 in M (64 rows each)
    const int warp_n = wid >> 1;      // 8 in N (32 cols each)

    float acc[4][4][4];
#pragma unroll
    for (int i = 0; i < 4; i++)
#pragma unroll
        for (int j = 0; j < 4; j++)
#pragma unroll
            for (int q = 0; q < 4; q++) acc[i][j][q] = 0.f;

    // cp.async mapping (rows are 64B = 32 halves; 512 threads)
    const int rA = tid >> 2, gA = tid & 3;
    const uint32_t dA = swz(rA, gA);
    const size_t aoff = (size_t)rA * lda + gA * 8;
    const int rB0 = rA, rB1 = rA + 128;
    const uint32_t dB0 = swz(rB0, gA), dB1 = swz(rB1, gA);
    const size_t boff0 = (size_t)rB0 * ldb + gA * 8;
    const size_t boff1 = (size_t)rB1 * ldb + gA * 8;

    auto load_stage = [&](int st, int kidx) {
        const int k0 = kidx * BK;
        const uint32_t sd = sb + st * STAGE_BY;
        cpa16(sd + dA, Ah_ + aoff + k0);
        if (THREE) cpa16(sd + OFF_AL + dA, Al_ + aoff + k0);
        cpa16(sd + OFF_BH + dB0, Bh_ + boff0 + k0);
        cpa16(sd + OFF_BH + dB1, Bh_ + boff1 + k0);
        cpa16(sd + OFF_BL + dB0, Bl_ + boff0 + k0);
        cpa16(sd + OFF_BL + dB1, Bl_ + boff1 + k0);
    };

    const int kt = K / BK;
#pragma unroll
    for (int s = 0; s < 3; s++) {
        load_stage(s, s);
        CP_COMMIT();
    }

    const uint32_t a_row = warp_m * 64 + (lane & 7) + (((lane >> 3) & 1) << 3);
    const uint32_t a_gb  = lane >> 4;
    const uint32_t b_row = warp_n * 32 + (lane & 7) + ((lane >> 4) << 3);
    const uint32_t b_gb  = (lane >> 3) & 1;

    for (int it = 0; it < kt; it++) {
        if (BS == 1) {
            CP_WAIT(2);
            __syncthreads();
        } else {
            if ((it & 1) == 0) {
                CP_WAIT(1);
                __syncthreads();
            }
        }

        const int nf = it + 3;
        if (nf < kt) load_stage(nf % STG, nf);
        CP_COMMIT();

        const uint32_t st = sb + (it % STG) * STAGE_BY;
#pragma unroll
        for (int ks = 0; ks < 2; ks++) {
            const uint32_t ag = ks * 2 + a_gb;
            const uint32_t bg = ks * 2 + b_gb;
            uint32_t ah[4][4], al[4][4];
#pragma unroll
            for (int mt = 0; mt < 4; mt++) {
                const uint32_t ad = st + swz(a_row + mt * 16, ag);
                LDSM4(ah[mt], ad);
                if (THREE) LDSM4(al[mt], ad + OFF_AL);
            }
            uint32_t bh[2][4], bl[2][4];
#pragma unroll
            for (int nc = 0; nc < 2; nc++) {
                const uint32_t bd = st + swz(b_row + nc * 16, bg);
                LDSM4(bh[nc], bd + OFF_BH);
                LDSM4(bl[nc], bd + OFF_BL);
            }
#pragma unroll
            for (int mt = 0; mt < 4; mt++)
#pragma unroll
                for (int nt = 0; nt < 4; nt++) {
                    const int nc = nt >> 1, h = nt & 1;
                    mma_f16(acc[mt][nt], ah[mt], bh[nc][h * 2], bh[nc][h * 2 + 1]);
                }
#pragma unroll
            for (int mt = 0; mt < 4; mt++)
#pragma unroll
                for (int nt = 0; nt < 4; nt++) {
                    const int nc = nt >> 1, h = nt & 1;
                    mma_f16(acc[mt][nt], ah[mt], bl[nc][h * 2], bl[nc][h * 2 + 1]);
                }
            if (THREE) {
#pragma unroll
                for (int mt = 0; mt < 4; mt++)
#pragma unroll
                    for (int nt = 0; nt < 4; nt++) {
                        const int nc = nt >> 1, h = nt & 1;
                        mma_f16(acc[mt][nt], al[mt], bh[nc][h * 2], bh[nc][h * 2 + 1]);
                    }
            }
        }
    }

    // Epilogue: warp tile 64x32
#pragma unroll
    for (int mt = 0; mt < 4; mt++) {
        const int r = warp_m * 64 + mt * 16 + (lane >> 2);
#pragma unroll
        for (int nt = 0; nt < 4; nt++) {
            const int c = warp_n * 32 + nt * 8 + (lane & 3) * 2;
            float v00 = acc[mt][nt][0], v01 = acc[mt][nt][1];
            float v10 = acc[mt][nt][2], v11 = acc[mt][nt][3];
            if (EPI == 0 || EPI == 2) {
                float2 bb = __ldg((const float2*)(bias + c));
                v00 += bb.x; v01 += bb.y; v10 += bb.x; v11 += bb.y;
            }
            if (EPI == 2) {
                __half2 l0, l1;
                __half2 h0 = split_hl(v00, v01, l0);
                __half2 h1 = split_hl(v10, v11, l1);
                *(__half2*)(Ch + (size_t)r * ldc + c) = h0;
                *(__half2*)(Ch + (size_t)(r + 8) * ldc + c) = h1;
                *(__half2*)(Cl + (size_t)r * ldc + c) = l0;
                *(__half2*)(Cl + (size_t)(r + 8) * ldc + c) = l1;
            } else {
                float2 s;
                s.x = v00; s.y = v01;
                *(float2*)(C + (size_t)r * ldc + c) = s;
                s.x = v10; s.y = v11;
                *(float2*)(C + (size_t)(r + 8) * ldc + c) = s;
            }
        }
    }
}

// Supertile remap for L2 reuse (G must divide gridDim.y)
__device__ __forceinline__ void remap_xy(int G, int& bx, int& by) {
    int lin = blockIdx.y * gridDim.x + blockIdx.x;
    int per = G * gridDim.x;
    int grp = lin / per, rem = lin % per;
    by = grp * G + (rem % G);
    bx = rem / G;
}

// ---------------------------------------------------------------------------
// Conversion payload: one 1024-block slab converts a full weight matrix
// (hi/lo split).  Each block handles 8192 consecutive float4s.
// ---------------------------------------------------------------------------
__device__ __forceinline__ void conv_w_block(const float* __restrict__ src,
                                             __half* __restrict__ h,
                                             __half* __restrict__ l)
{
    const int blin = blockIdx.y * gridDim.x + blockIdx.x;   // 0..1023
    const size_t base = (size_t)blin * 8192;
    const float4* s4 = (const float4*)src;
    for (int i = threadIdx.x; i < 8192; i += NTHREAD) {
        const size_t idx = base + i;
        float4 v = s4[idx];
        __half2 l0, l1;
        __half2 h0 = split_hl(v.x, v.y, l0);
        __half2 h1 = split_hl(v.z, v.w, l1);
        __half2* hp = (__half2*)(h + idx * 4);
        hp[0] = h0; hp[1] = h1;
        __half2* lp = (__half2*)(l + idx * 4);
        lp[0] = l0; lp[1] = l1;
    }
}

// ---------------------------------------------------------------------------
// GEMM kernels (CTA tile 128M x 256N, 512 threads)
// proj_q / proj_k carry the NEXT weight's conversion as z=1 payload blocks.
// ---------------------------------------------------------------------------
__global__ void __launch_bounds__(NTHREAD, 1)
proj_q_kernel(const float* __restrict__ bias, const float* __restrict__ wk_src)
{
    if (blockIdx.z == 1) {          // payload: convert wk for the next launch
        conv_w_block(wk_src, g_wkh, g_wkl);
        return;
    }
    int bx, by; remap_xy(8, bx, by);
    const int tm = by * 128, tn = bx * 256;
    gemm_body<2, false, 5, 2>(g_xh + (size_t)tm * D_MODEL, nullptr, D_MODEL,
                              g_wqh + (size_t)tn * D_MODEL, g_wql + (size_t)tn * D_MODEL, D_MODEL,
                              D_MODEL, nullptr, TWO_D,
                              g_qh + (size_t)tm * TWO_D + tn, g_ql + (size_t)tm * TWO_D + tn,
                              bias + tn);
}

__global__ void __launch_bounds__(NTHREAD, 1)
proj_k_kernel(const float* __restrict__ bias, const float* __restrict__ wv_src)
{
    if (blockIdx.z == 1) {          // payload: convert wv for the next launch
        conv_w_block(wv_src, g_wvh, g_wvl);
        return;
    }
    int bx, by; remap_xy(8, bx, by);
    const int tm = by * 128, tn = bx * 256;
    gemm_body<2, false, 5, 2>(g_xh + (size_t)tm * D_MODEL, nullptr, D_MODEL,
                              g_wkh + (size_t)tn * D_MODEL, g_wkl + (size_t)tn * D_MODEL, D_MODEL,
                              D_MODEL, nullptr, TWO_D,
                              g_kh + (size_t)tm * TWO_D + tn, g_kl + (size_t)tm * TWO_D + tn,
                              bias + tn);
}

__global__ void __launch_bounds__(NTHREAD, 1)
proj_v_kernel(const float* __restrict__ bias)
{
    int bx, by; remap_xy(8, bx, by);
    const int tm = by * 128, tn = bx * 256;
    gemm_body<2, false, 5, 2>(g_xh + (size_t)tm * D_MODEL, nullptr, D_MODEL,
                              g_wvh + (size_t)tn * D_MODEL, g_wvl + (size_t)tn * D_MODEL, D_MODEL,
                              D_MODEL, nullptr, TWO_D,
                              g_vh + (size_t)tm * TWO_D + tn, g_vl + (size_t)tm * TWO_D + tn,
                              bias + tn);
}

// Logits GEMM + V-transpose payload in one launch.
// grid (2, 4, 16 + 64): z<16 -> logits tile, z>=16 -> transpose blocks that
// run on the SMs logits leaves idle (logits occupies only 128 of 148 SMs).
__global__ void __launch_bounds__(NTHREAD, 1)
logits_tr_kernel()
{
    if (blockIdx.z >= 16) {
        // ---- transpose payload: vt[b][n][s] = v[b][s][n], hi+lo ----
        extern __shared__ char dsm_raw[];
        const int tj = ((blockIdx.z - 16) * 4 + blockIdx.y) * 2 + blockIdx.x; // 0..511
        const int slot = threadIdx.x >> 8;         // 2 slots of 256 threads
        const int stid = threadIdx.x & 255;
        const int tx = stid & 31, ty = stid >> 5;  // 32 x 8
        __half (*th)[34] = (__half(*)[34])(dsm_raw + slot * 4608);
        __half (*tl)[34] = (__half(*)[34])(dsm_raw + slot * 4608 + 2304);
        for (int itr = 0; itr < 32; itr++) {
            const int job = tj * 64 + itr * 2 + slot;     // 0..32767
            const int nx = job & 255;                     // TWO_D/32
            const int sy = (job >> 8) & 15;               // SEQ/32
            const int b  = job >> 12;                     // NB
            const size_t sbase = (size_t)b * SEQ * TWO_D;
            const int s0 = sy * 32, n0 = nx * 32;
#pragma unroll
            for (int i = ty; i < 32; i += 8) {
                size_t o = sbase + (size_t)(s0 + i) * TWO_D + n0 + tx;
                th[i][tx] = g_vh[o];
                tl[i][tx] = g_vl[o];
            }
            __syncthreads();
            const size_t dbase = (size_t)b * TWO_D * SEQ;
#pragma unroll
            for (int i = ty; i < 32; i += 8) {
                size_t o = dbase + (size_t)(n0 + i) * SEQ + s0 + tx;
                g_vth[o] = th[tx][i];
                g_vtl[o] = tl[tx][i];
            }
            __syncthreads();
        }
        return;
    }
    // ---- logits GEMM ----
    const int bz = blockIdx.z;
    const int b = bz >> 1, pair = bz & 1;
    const int tm = blockIdx.y * 128, tn = blockIdx.x * 256;
    const size_t qoff = (size_t)b * SEQ * TWO_D + (size_t)pair * D_MODEL;
    float* C = (pair ? g_l2 : g_l1) + (size_t)b * SEQ * SEQ
             + (size_t)tm * SEQ + tn;
    gemm_body<1, true, 4, 1>(g_qh + qoff + (size_t)tm * TWO_D,
                             g_ql + qoff + (size_t)tm * TWO_D, TWO_D,
                             g_kh + qoff + (size_t)tn * TWO_D,
                             g_kl + qoff + (size_t)tn * TWO_D, TWO_D,
                             D_MODEL, C, SEQ, nullptr, nullptr, nullptr);
}

__global__ void __launch_bounds__(NTHREAD, 1)
out_gemm_kernel(float* __restrict__ out)
{
    const int b = blockIdx.z;
    int bx, by; remap_xy(4, bx, by);
    const int tm = by * 128, tn = bx * 256;
    const size_t soff = (size_t)b * SEQ * SEQ + (size_t)tm * SEQ;
    const size_t voff = (size_t)b * TWO_D * SEQ + (size_t)tn * SEQ;
    gemm_body<1, true, 4, 1>(g_sch + soff, g_scl + soff, SEQ,
                             g_vth + voff, g_vtl + voff, SEQ,
                             SEQ, out + (size_t)b * SEQ * TWO_D + (size_t)tm * TWO_D + tn, TWO_D,
                             nullptr, nullptr, nullptr);
}

// ---------------------------------------------------------------------------
// Support kernels
// ---------------------------------------------------------------------------
// Launch-0 conversion: z=0 -> x (hi only), z=1 -> wq (hi+lo)
__global__ void __launch_bounds__(256)
conv_xq_kernel(const float* __restrict__ x, const float* __restrict__ wq,
               int n4x, int n4w)
{
    const int idx = blockIdx.x * 256 + threadIdx.x;
    if (blockIdx.z == 0) {
        if (idx >= n4x) return;
        float4 v = ((const float4*)x)[idx];
        __half2* hp = (__half2*)(g_xh + (size_t)idx * 4);
        hp[0] = __halves2half2(__float2half_rn(v.x), __float2half_rn(v.y));
        hp[1] = __halves2half2(__float2half_rn(v.z), __float2half_rn(v.w));
        return;
    }
    if (idx >= n4w) return;
    float4 v = ((const float4*)wq)[idx];
    __half2 l0, l1;
    __half2 h0 = split_hl(v.x, v.y, l0);
    __half2 h1 = split_hl(v.z, v.w, l1);
    __half2* hp = (__half2*)(g_wqh + (size_t)idx * 4);
    hp[0] = h0; hp[1] = h1;
    __half2* lp = (__half2*)(g_wql + (size_t)idx * 4);
    lp[0] = l0; lp[1] = l1;
}

// Softmax over key axis + differential combine; writes f16 hi+lo scores
__global__ void __launch_bounds__(256)
softmax_combine_kernel(const float* __restrict__ lq1, const float* __restrict__ lk1,
                       const float* __restrict__ lq2, const float* __restrict__ lk2)
{
    const int r = blockIdx.x, b = blockIdx.y;
    const size_t off = ((size_t)b * SEQ + r) * SEQ;
    const float scale = 0.04419417382415922f;  // 1/sqrt(512)
    const int tid = threadIdx.x;
    const int lane = tid & 31, warp = tid >> 5;

    float v1a = g_l1[off + tid]       * scale;
    float v1b = g_l1[off + tid + 256] * scale;
    float v2a = g_l2[off + tid]       * scale;
    float v2b = g_l2[off + tid + 256] * scale;

    __shared__ float red1[8], red2[8];

    float m1 = fmaxf(v1a, v1b), m2 = fmaxf(v2a, v2b);
#pragma unroll
    for (int o = 16; o; o >>= 1) {
        m1 = fmaxf(m1, __shfl_xor_sync(0xffffffffu, m1, o));
        m2 = fmaxf(m2, __shfl_xor_sync(0xffffffffu, m2, o));
    }
    if (lane == 0) { red1[warp] = m1; red2[warp] = m2; }
    __syncthreads();
    m1 = red1[0]; m2 = red2[0];
#pragma unroll
    for (int i = 1; i < 8; i++) { m1 = fmaxf(m1, red1[i]); m2 = fmaxf(m2, red2[i]); }
    __syncthreads();

    float e1a = expf(v1a - m1), e1b = expf(v1b - m1);
    float e2a = expf(v2a - m2), e2b = expf(v2b - m2);
    float s1 = e1a + e1b, s2 = e2a + e2b;
#pragma unroll
    for (int o = 16; o; o >>= 1) {
        s1 += __shfl_xor_sync(0xffffffffu, s1, o);
        s2 += __shfl_xor_sync(0xffffffffu, s2, o);
    }
    if (lane == 0) { red1[warp] = s1; red2[warp] = s2; }
    __syncthreads();
    s1 = 0.f; s2 = 0.f;
#pragma unroll
    for (int i = 0; i < 8; i++) { s1 += red1[i]; s2 += red2[i]; }
    const float inv1 = 1.f / s1, inv2 = 1.f / s2;

#pragma unroll
    for (int half = 0; half < 2; half++) {
        const int k = tid + half * 256;
        float e1 = half ? e1b : e1a;
        float e2 = half ? e2b : e2a;
        float lam = expf(lq1[k] * lk1[k]) - expf(lq2[k] * lk2[k]) + LAMBDA_INIT;
        float v = e1 * inv1 - lam * (e2 * inv2);
        __half hh = __float2half_rn(v);
        g_sch[off + k] = hh;
        g_scl[off + k] = __float2half_rn(v - __half2float(hh));
    }
}

// ---------------------------------------------------------------------------
extern "C" void kernel_launch(void* const* d_in, const int* in_sizes, int n_in,
                              void* d_out, int out_size)
{
    const float* x    = (const float*)d_in[0];
    const float* wq_w = (const float*)d_in[1];
    const float* wq_b = (const float*)d_in[2];
    const float* wk_w = (const float*)d_in[3];
    const float* wk_b = (const float*)d_in[4];
    const float* wv_w = (const float*)d_in[5];
    const float* wv_b = (const float*)d_in[6];
    const float* lq1  = (const float*)d_in[7];
    const float* lk1  = (const float*)d_in[8];
    const float* lq2  = (const float*)d_in[9];
    const float* lk2  = (const float*)d_in[10];
    float* out = (float*)d_out;

    cudaFuncSetAttribute(proj_q_kernel,   cudaFuncAttributeMaxDynamicSharedMemorySize, DSMEM_BYTES_2P);
    cudaFuncSetAttribute(proj_k_kernel,   cudaFuncAttributeMaxDynamicSharedMemorySize, DSMEM_BYTES_2P);
    cudaFuncSetAttribute(proj_v_kernel,   cudaFuncAttributeMaxDynamicSharedMemorySize, DSMEM_BYTES_2P);
    cudaFuncSetAttribute(logits_tr_kernel, cudaFuncAttributeMaxDynamicSharedMemorySize, DSMEM_BYTES_3P);
    cudaFuncSetAttribute(out_gemm_kernel, cudaFuncAttributeMaxDynamicSharedMemorySize, DSMEM_BYTES_3P);

    const int n4x = 4096 * 4096 / 4;
    const int n4w = TWO_D * 4096 / 4;

    // 0: convert x (hi) + wq (hi/lo)
    conv_xq_kernel<<<dim3(n4w / 256, 1, 2), 256>>>(x, wq_w, n4x, n4w);

    dim3 projGridP(TWO_D / 256, (NB * SEQ) / 128, 2);   // (32, 32, 2): z=1 payload
    dim3 projGrid (TWO_D / 256, (NB * SEQ) / 128, 1);   // pure

    proj_q_kernel<<<projGridP, NTHREAD, DSMEM_BYTES_2P>>>(wq_b, wk_w);  // 1 (+conv wk)
    proj_k_kernel<<<projGridP, NTHREAD, DSMEM_BYTES_2P>>>(wk_b, wv_w);  // 2 (+conv wv)
    proj_v_kernel<<<projGrid,  NTHREAD, DSMEM_BYTES_2P>>>(wv_b);        // 3 <- profiled

    dim3 logitsGrid(SEQ / 256, SEQ / 128, 16 + 64);     // (2, 4, 80): z>=16 transpose
    logits_tr_kernel<<<logitsGrid, NTHREAD, DSMEM_BYTES_3P>>>();        // 4

    dim3 smGrid(SEQ, NB);
    softmax_combine_kernel<<<smGrid, 256>>>(lq1, lk1, lq2, lk2);        // 5

    dim3 outGrid(TWO_D / 256, SEQ / 128, NB);           // (32, 4, 8)
    out_gemm_kernel<<<outGrid, NTHREAD, DSMEM_BYTES_3P>>>(out);         // 6
}

// round 14
// speedup vs baseline: 1.0812x; 1.0812x over previous
#include <cuda_runtime.h>
#include <cuda_fp16.h>
#include <cstdint>
#include <math.h>

// Problem constants
#define D_MODEL 4096
#define TWO_D   8192
#define NB      8
#define SEQ     512
#define LAMBDA_INIT 0.8f

// ---------------------------------------------------------------------------
// Scratch (static device globals; no runtime allocation allowed)
// ---------------------------------------------------------------------------
__device__ __align__(256) __half g_xh [(size_t)4096 * 4096];
__device__ __align__(256) __half g_wqh[(size_t)TWO_D * 4096];
__device__ __align__(256) __half g_wql[(size_t)TWO_D * 4096];
__device__ __align__(256) __half g_wkh[(size_t)TWO_D * 4096];
__device__ __align__(256) __half g_wkl[(size_t)TWO_D * 4096];
__device__ __align__(256) __half g_wvh[(size_t)TWO_D * 4096];
__device__ __align__(256) __half g_wvl[(size_t)TWO_D * 4096];
__device__ __align__(256) __half g_qh [(size_t)NB * SEQ * TWO_D];
__device__ __align__(256) __half g_ql [(size_t)NB * SEQ * TWO_D];
__device__ __align__(256) __half g_kh [(size_t)NB * SEQ * TWO_D];
__device__ __align__(256) __half g_kl [(size_t)NB * SEQ * TWO_D];
__device__ __align__(256) __half g_vh [(size_t)NB * SEQ * TWO_D];
__device__ __align__(256) __half g_vl [(size_t)NB * SEQ * TWO_D];
__device__ __align__(256) __half g_vth[(size_t)NB * TWO_D * SEQ];
__device__ __align__(256) __half g_vtl[(size_t)NB * TWO_D * SEQ];
__device__ __align__(256) float  g_l1 [(size_t)NB * SEQ * SEQ];
__device__ __align__(256) float  g_l2 [(size_t)NB * SEQ * SEQ];
__device__ __align__(256) __half g_sch[(size_t)NB * SEQ * SEQ];
__device__ __align__(256) __half g_scl[(size_t)NB * SEQ * SEQ];

// ---------------------------------------------------------------------------
// PTX primitives (arch-neutral: sm_80+)
// ---------------------------------------------------------------------------
__device__ __forceinline__ uint32_t smem_u32(const void* p) {
    uint32_t a;
    asm("{ .reg .u64 t; cvta.to.shared.u64 t, %1; cvt.u32.u64 %0, t; }"
        : "=r"(a) : "l"(p));
    return a;
}

__device__ __forceinline__ void cpa16(uint32_t dst, const void* src) {
    asm volatile("cp.async.cg.shared.global [%0], [%1], 16;\n"
                 :: "r"(dst), "l"(src));
}
#define CP_COMMIT() asm volatile("cp.async.commit_group;\n" ::: "memory")
#define CP_WAIT(N)  asm volatile("cp.async.wait_group %0;\n" :: "n"(N) : "memory")

#define LDSM4(R, addr) \
    asm volatile("ldmatrix.sync.aligned.m8n8.x4.shared.b16 {%0,%1,%2,%3}, [%4];" \
        : "=r"((R)[0]), "=r"((R)[1]), "=r"((R)[2]), "=r"((R)[3]) : "r"(addr))

__device__ __forceinline__ void mma_f16(float* c, const uint32_t* a,
                                        uint32_t b0, uint32_t b1) {
    asm volatile(
        "mma.sync.aligned.m16n8k16.row.col.f32.f16.f16.f32 "
        "{%0,%1,%2,%3}, {%4,%5,%6,%7}, {%8,%9}, {%0,%1,%2,%3};"
        : "+f"(c[0]), "+f"(c[1]), "+f"(c[2]), "+f"(c[3])
        : "r"(a[0]), "r"(a[1]), "r"(a[2]), "r"(a[3]), "r"(b0), "r"(b1));
}

// Swizzled smem byte offset: tile row r (64B rows), 16B-granule g
__device__ __forceinline__ uint32_t swz(uint32_t r, uint32_t g) {
    return r * 64u + (((g ^ ((r >> 1) & 3u)) << 4));
}

__device__ __forceinline__ __half2 split_hl(float a, float b, __half2& lo) {
    __half ha = __float2half_rn(a), hb = __float2half_rn(b);
    lo = __halves2half2(__float2half_rn(a - __half2float(ha)),
                        __float2half_rn(b - __half2float(hb)));
    return __halves2half2(ha, hb);
}

// ---------------------------------------------------------------------------
// Projection GEMM: C[128,128] = A[128,K] @ B[128,K]^T, fp16 2-product
// (AhBh + AhBl, A hi-only).  256 threads, 8 warps, warp tile 64x32.
// 4 stages x 24KB = 96KB smem -> TWO CTAs per SM (epilogue/prologue/barrier
// shadows of one CTA covered by the other's mainloop).
// Writes f16 hi/lo + bias.
// ---------------------------------------------------------------------------
#define BK       32
#define NTHREAD  512
#define PSTAGE   24576
#define POFF_BH  8192
#define POFF_BL  16384
#define DSMEM_BYTES_P (4 * PSTAGE + 1024)        // 99,328 * 2 CTAs = 198,656
#define DSMEM_BYTES_3P (4 * 49152 + 1024)

__device__ __forceinline__ void gemm_body_proj(
    const __half* __restrict__ Ah_, int lda,
    const __half* __restrict__ Bh_, const __half* __restrict__ Bl_, int ldb,
    int K, int ldc,
    __half* __restrict__ Ch, __half* __restrict__ Cl,
    const float* __restrict__ bias)
{
    extern __shared__ char dsm_raw[];
    const uint32_t sb = (smem_u32(dsm_raw) + 1023u) & ~1023u;

    const int tid  = threadIdx.x;
    const int wid  = tid >> 5;
    const int lane = tid & 31;
    const int warp_m = wid & 1;       // 2 in M (64 rows each)
    const int warp_n = wid >> 1;      // 4 in N (32 cols each)

    float acc[4][4][4];
#pragma unroll
    for (int i = 0; i < 4; i++)
#pragma unroll
        for (int j = 0; j < 4; j++)
#pragma unroll
            for (int q = 0; q < 4; q++) acc[i][j][q] = 0.f;

    // cp.async mapping: 256 threads; A/Bh/Bl each 128 rows x 4 granules
    // = 512 granules -> 2 per thread per tile.
    const int rA = tid >> 2, gA = tid & 3;                 // rows rA, rA+64
    const uint32_t d0 = swz(rA, gA), d1 = swz(rA + 64, gA);
    const size_t aoff0 = (size_t)rA * lda + gA * 8;
    const size_t aoff1 = (size_t)(rA + 64) * lda + gA * 8;
    const size_t boff0 = (size_t)rA * ldb + gA * 8;
    const size_t boff1 = (size_t)(rA + 64) * ldb + gA * 8;

    auto load_stage = [&](int st, int kidx) {
        const int k0 = kidx * BK;
        const uint32_t sd = sb + st * PSTAGE;
        cpa16(sd + d0, Ah_ + aoff0 + k0);
        cpa16(sd + d1, Ah_ + aoff1 + k0);
        cpa16(sd + POFF_BH + d0, Bh_ + boff0 + k0);
        cpa16(sd + POFF_BH + d1, Bh_ + boff1 + k0);
        cpa16(sd + POFF_BL + d0, Bl_ + boff0 + k0);
        cpa16(sd + POFF_BL + d1, Bl_ + boff1 + k0);
    };

    const int kt = K / BK;
#pragma unroll
    for (int s = 0; s < 3; s++) {
        load_stage(s, s);
        CP_COMMIT();
    }

    const uint32_t a_row = warp_m * 64 + (lane & 7) + (((lane >> 3) & 1) << 3);
    const uint32_t a_gb  = lane >> 4;
    const uint32_t b_row = warp_n * 32 + (lane & 7) + ((lane >> 4) << 3);
    const uint32_t b_gb  = (lane >> 3) & 1;

    for (int it = 0; it < kt; it++) {
        CP_WAIT(2);
        __syncthreads();

        const int nf = it + 3;
        if (nf < kt) load_stage(nf & 3, nf);
        CP_COMMIT();

        const uint32_t st = sb + (it & 3) * PSTAGE;
#pragma unroll
        for (int ks = 0; ks < 2; ks++) {
            const uint32_t ag = ks * 2 + a_gb;
            const uint32_t bg = ks * 2 + b_gb;
            uint32_t ah[4][4];
#pragma unroll
            for (int mt = 0; mt < 4; mt++)
                LDSM4(ah[mt], st + swz(a_row + mt * 16, ag));
            uint32_t bh[2][4], bl[2][4];
#pragma unroll
            for (int nc = 0; nc < 2; nc++) {
                const uint32_t bd = st + swz(b_row + nc * 16, bg);
                LDSM4(bh[nc], bd + POFF_BH);
                LDSM4(bl[nc], bd + POFF_BL);
            }
#pragma unroll
            for (int mt = 0; mt < 4; mt++)
#pragma unroll
                for (int nt = 0; nt < 4; nt++) {
                    const int nc = nt >> 1, h = nt & 1;
                    mma_f16(acc[mt][nt], ah[mt], bh[nc][h * 2], bh[nc][h * 2 + 1]);
                }
#pragma unroll
            for (int mt = 0; mt < 4; mt++)
#pragma unroll
                for (int nt = 0; nt < 4; nt++) {
                    const int nc = nt >> 1, h = nt & 1;
                    mma_f16(acc[mt][nt], ah[mt], bl[nc][h * 2], bl[nc][h * 2 + 1]);
                }
        }
    }

    // Epilogue: f16 hi/lo + bias
#pragma unroll
    for (int mt = 0; mt < 4; mt++) {
        const int r = warp_m * 64 + mt * 16 + (lane >> 2);
#pragma unroll
        for (int nt = 0; nt < 4; nt++) {
            const int c = warp_n * 32 + nt * 8 + (lane & 3) * 2;
            float2 bb = __ldg((const float2*)(bias + c));
            float v00 = acc[mt][nt][0] + bb.x, v01 = acc[mt][nt][1] + bb.y;
            float v10 = acc[mt][nt][2] + bb.x, v11 = acc[mt][nt][3] + bb.y;
            __half2 l0, l1;
            __half2 h0 = split_hl(v00, v01, l0);
            __half2 h1 = split_hl(v10, v11, l1);
            *(__half2*)(Ch + (size_t)r * ldc + c) = h0;
            *(__half2*)(Ch + (size_t)(r + 8) * ldc + c) = h1;
            *(__half2*)(Cl + (size_t)r * ldc + c) = l0;
            *(__half2*)(Cl + (size_t)(r + 8) * ldc + c) = l1;
        }
    }
}

// ---------------------------------------------------------------------------
// Generic GEMM (logits/output): C[128,256] = A[128,K] @ B[256,K]^T,
// 3-product (AhBh + AhBl + AlBh), 512 threads, fp32 epilogue.
// ---------------------------------------------------------------------------
__device__ __forceinline__ void gemm_body_3p(
    const __half* __restrict__ Ah_, const __half* __restrict__ Al_, int lda,
    const __half* __restrict__ Bh_, const __half* __restrict__ Bl_, int ldb,
    int K, float* __restrict__ C, int ldc)
{
    constexpr uint32_t OFF_AL   = 8192;
    constexpr uint32_t OFF_BH   = 16384;
    constexpr uint32_t OFF_BL   = 32768;
    constexpr uint32_t STAGE_BY = 49152;

    extern __shared__ char dsm_raw[];
    const uint32_t sb = (smem_u32(dsm_raw) + 1023u) & ~1023u;

    const int tid  = threadIdx.x;
    const int wid  = tid >> 5;
    const int lane = tid & 31;
    const int warp_m = wid & 1;
    const int warp_n = wid >> 1;      // 8 in N (32 cols each)

    float acc[4][4][4];
#pragma unroll
    for (int i = 0; i < 4; i++)
#pragma unroll
        for (int j = 0; j < 4; j++)
#pragma unroll
            for (int q = 0; q < 4; q++) acc[i][j][q] = 0.f;

    const int rA = tid >> 2, gA = tid & 3;
    const uint32_t dA = swz(rA, gA);
    const size_t aoff = (size_t)rA * lda + gA * 8;
    const int rB0 = rA, rB1 = rA + 128;
    const uint32_t dB0 = swz(rB0, gA), dB1 = swz(rB1, gA);
    const size_t boff0 = (size_t)rB0 * ldb + gA * 8;
    const size_t boff1 = (size_t)rB1 * ldb + gA * 8;

    auto load_stage = [&](int st, int kidx) {
        const int k0 = kidx * BK;
        const uint32_t sd = sb + st * STAGE_BY;
        cpa16(sd + dA, Ah_ + aoff + k0);
        cpa16(sd + OFF_AL + dA, Al_ + aoff + k0);
        cpa16(sd + OFF_BH + dB0, Bh_ + boff0 + k0);
        cpa16(sd + OFF_BH + dB1, Bh_ + boff1 + k0);
        cpa16(sd + OFF_BL + dB0, Bl_ + boff0 + k0);
        cpa16(sd + OFF_BL + dB1, Bl_ + boff1 + k0);
    };

    const int kt = K / BK;
#pragma unroll
    for (int s = 0; s < 3; s++) {
        load_stage(s, s);
        CP_COMMIT();
    }

    const uint32_t a_row = warp_m * 64 + (lane & 7) + (((lane >> 3) & 1) << 3);
    const uint32_t a_gb  = lane >> 4;
    const uint32_t b_row = warp_n * 32 + (lane & 7) + ((lane >> 4) << 3);
    const uint32_t b_gb  = (lane >> 3) & 1;

    for (int it = 0; it < kt; it++) {
        CP_WAIT(2);
        __syncthreads();

        const int nf = it + 3;
        if (nf < kt) load_stage(nf & 3, nf);
        CP_COMMIT();

        const uint32_t st = sb + (it & 3) * STAGE_BY;
#pragma unroll
        for (int ks = 0; ks < 2; ks++) {
            const uint32_t ag = ks * 2 + a_gb;
            const uint32_t bg = ks * 2 + b_gb;
            uint32_t ah[4][4], al[4][4];
#pragma unroll
            for (int mt = 0; mt < 4; mt++) {
                const uint32_t ad = st + swz(a_row + mt * 16, ag);
                LDSM4(ah[mt], ad);
                LDSM4(al[mt], ad + OFF_AL);
            }
            uint32_t bh[2][4], bl[2][4];
#pragma unroll
            for (int nc = 0; nc < 2; nc++) {
                const uint32_t bd = st + swz(b_row + nc * 16, bg);
                LDSM4(bh[nc], bd + OFF_BH);
                LDSM4(bl[nc], bd + OFF_BL);
            }
#pragma unroll
            for (int mt = 0; mt < 4; mt++)
#pragma unroll
                for (int nt = 0; nt < 4; nt++) {
                    const int nc = nt >> 1, h = nt & 1;
                    mma_f16(acc[mt][nt], ah[mt], bh[nc][h * 2], bh[nc][h * 2 + 1]);
                }
#pragma unroll
            for (int mt = 0; mt < 4; mt++)
#pragma unroll
                for (int nt = 0; nt < 4; nt++) {
                    const int nc = nt >> 1, h = nt & 1;
                    mma_f16(acc[mt][nt], ah[mt], bl[nc][h * 2], bl[nc][h * 2 + 1]);
                }
#pragma unroll
            for (int mt = 0; mt < 4; mt++)
#pragma unroll
                for (int nt = 0; nt < 4; nt++) {
                    const int nc = nt >> 1, h = nt & 1;
                    mma_f16(acc[mt][nt], al[mt], bh[nc][h * 2], bh[nc][h * 2 + 1]);
                }
        }
    }

#pragma unroll
    for (int mt = 0; mt < 4; mt++) {
        const int r = warp_m * 64 + mt * 16 + (lane >> 2);
#pragma unroll
        for (int nt = 0; nt < 4; nt++) {
            const int c = warp_n * 32 + nt * 8 + (lane & 3) * 2;
            float2 s;
            s.x = acc[mt][nt][0]; s.y = acc[mt][nt][1];
            *(float2*)(C + (size_t)r * ldc + c) = s;
            s.x = acc[mt][nt][2]; s.y = acc[mt][nt][3];
            *(float2*)(C + (size_t)(r + 8) * ldc + c) = s;
        }
    }
}

// Supertile remap for L2 reuse (G must divide gridDim.y)
__device__ __forceinline__ void remap_xy(int G, int& bx, int& by) {
    int lin = blockIdx.y * gridDim.x + blockIdx.x;
    int per = G * gridDim.x;
    int grp = lin / per, rem = lin % per;
    by = grp * G + (rem % G);
    bx = rem / G;
}

// ---------------------------------------------------------------------------
// Conversion payload: grid z=1 slab converts a full weight matrix (hi/lo).
// ---------------------------------------------------------------------------
__device__ __forceinline__ void conv_w_block(const float* __restrict__ src,
                                             __half* __restrict__ h,
                                             __half* __restrict__ l)
{
    const int nblk = gridDim.x * gridDim.y;
    const int per = (TWO_D * 4096 / 4) / nblk;
    const int blin = blockIdx.y * gridDim.x + blockIdx.x;
    const size_t base = (size_t)blin * per;
    const float4* s4 = (const float4*)src;
    for (int i = threadIdx.x; i < per; i += blockDim.x) {
        const size_t idx = base + i;
        float4 v = s4[idx];
        __half2 l0, l1;
        __half2 h0 = split_hl(v.x, v.y, l0);
        __half2 h1 = split_hl(v.z, v.w, l1);
        __half2* hp = (__half2*)(h + idx * 4);
        hp[0] = h0; hp[1] = h1;
        __half2* lp = (__half2*)(l + idx * 4);
        lp[0] = l0; lp[1] = l1;
    }
}

// ---------------------------------------------------------------------------
// Projection kernels: CTA tile 128x128, 256 threads, 2 CTAs/SM.
// proj_q / proj_k carry the NEXT weight's conversion as z=1 payload.
// ---------------------------------------------------------------------------
__global__ void __launch_bounds__(256, 2)
proj_q_kernel(const float* __restrict__ bias, const float* __restrict__ wk_src)
{
    if (blockIdx.z == 1) { conv_w_block(wk_src, g_wkh, g_wkl); return; }
    int bx, by; remap_xy(8, bx, by);
    const int tm = by * 128, tn = bx * 128;
    gemm_body_proj(g_xh + (size_t)tm * D_MODEL, D_MODEL,
                   g_wqh + (size_t)tn * D_MODEL, g_wql + (size_t)tn * D_MODEL, D_MODEL,
                   D_MODEL, TWO_D,
                   g_qh + (size_t)tm * TWO_D + tn, g_ql + (size_t)tm * TWO_D + tn,
                   bias + tn);
}

__global__ void __launch_bounds__(256, 2)
proj_k_kernel(const float* __restrict__ bias, const float* __restrict__ wv_src)
{
    if (blockIdx.z == 1) { conv_w_block(wv_src, g_wvh, g_wvl); return; }
    int bx, by; remap_xy(8, bx, by);
    const int tm = by * 128, tn = bx * 128;
    gemm_body_proj(g_xh + (size_t)tm * D_MODEL, D_MODEL,
                   g_wkh + (size_t)tn * D_MODEL, g_wkl + (size_t)tn * D_MODEL, D_MODEL,
                   D_MODEL, TWO_D,
                   g_kh + (size_t)tm * TWO_D + tn, g_kl + (size_t)tm * TWO_D + tn,
                   bias + tn);
}

__global__ void __launch_bounds__(256, 2)
proj_v_kernel(const float* __restrict__ bias)
{
    int bx, by; remap_xy(8, bx, by);
    const int tm = by * 128, tn = bx * 128;
    gemm_body_proj(g_xh + (size_t)tm * D_MODEL, D_MODEL,
                   g_wvh + (size_t)tn * D_MODEL, g_wvl + (size_t)tn * D_MODEL, D_MODEL,
                   D_MODEL, TWO_D,
                   g_vh + (size_t)tm * TWO_D + tn, g_vl + (size_t)tm * TWO_D + tn,
                   bias + tn);
}

// ---------------------------------------------------------------------------
// Logits GEMM + V-transpose payload (z >= 16), 512 threads, 1 CTA/SM.
// ---------------------------------------------------------------------------
__global__ void __launch_bounds__(NTHREAD, 1)
logits_tr_kernel()
{
    if (blockIdx.z >= 16) {
        extern __shared__ char dsm_raw[];
        const int tj = ((blockIdx.z - 16) * 4 + blockIdx.y) * 2 + blockIdx.x; // 0..511
        const int slot = threadIdx.x >> 8;
        const int stid = threadIdx.x & 255;
        const int tx = stid & 31, ty = stid >> 5;
        __half (*th)[34] = (__half(*)[34])(dsm_raw + slot * 4608);
        __half (*tl)[34] = (__half(*)[34])(dsm_raw + slot * 4608 + 2304);
        for (int itr = 0; itr < 32; itr++) {
            const int job = tj * 64 + itr * 2 + slot;
            const int nx = job & 255;
            const int sy = (job >> 8) & 15;
            const int b  = job >> 12;
            const size_t sbase = (size_t)b * SEQ * TWO_D;
            const int s0 = sy * 32, n0 = nx * 32;
#pragma unroll
            for (int i = ty; i < 32; i += 8) {
                size_t o = sbase + (size_t)(s0 + i) * TWO_D + n0 + tx;
                th[i][tx] = g_vh[o];
                tl[i][tx] = g_vl[o];
            }
            __syncthreads();
            const size_t dbase = (size_t)b * TWO_D * SEQ;
#pragma unroll
            for (int i = ty; i < 32; i += 8) {
                size_t o = dbase + (size_t)(n0 + i) * SEQ + s0 + tx;
                g_vth[o] = th[tx][i];
                g_vtl[o] = tl[tx][i];
            }
            __syncthreads();
        }
        return;
    }
    const int bz = blockIdx.z;
    const int b = bz >> 1, pair = bz & 1;
    const int tm = blockIdx.y * 128, tn = blockIdx.x * 256;
    const size_t qoff = (size_t)b * SEQ * TWO_D + (size_t)pair * D_MODEL;
    float* C = (pair ? g_l2 : g_l1) + (size_t)b * SEQ * SEQ
             + (size_t)tm * SEQ + tn;
    gemm_body_3p(g_qh + qoff + (size_t)tm * TWO_D,
                 g_ql + qoff + (size_t)tm * TWO_D, TWO_D,
                 g_kh + qoff + (size_t)tn * TWO_D,
                 g_kl + qoff + (size_t)tn * TWO_D, TWO_D,
                 D_MODEL, C, SEQ);
}

__global__ void __launch_bounds__(NTHREAD, 1)
out_gemm_kernel(float* __restrict__ out)
{
    const int b = blockIdx.z;
    int bx, by; remap_xy(4, bx, by);
    const int tm = by * 128, tn = bx * 256;
    const size_t soff = (size_t)b * SEQ * SEQ + (size_t)tm * SEQ;
    const size_t voff = (size_t)b * TWO_D * SEQ + (size_t)tn * SEQ;
    gemm_body_3p(g_sch + soff, g_scl + soff, SEQ,
                 g_vth + voff, g_vtl + voff, SEQ,
                 SEQ, out + (size_t)b * SEQ * TWO_D + (size_t)tm * TWO_D + tn, TWO_D);
}

// ---------------------------------------------------------------------------
// Support kernels
// ---------------------------------------------------------------------------
__global__ void __launch_bounds__(256)
conv_xq_kernel(const float* __restrict__ x, const float* __restrict__ wq,
               int n4x, int n4w)
{
    const int idx = blockIdx.x * 256 + threadIdx.x;
    if (blockIdx.z == 0) {
        if (idx >= n4x) return;
        float4 v = ((const float4*)x)[idx];
        __half2* hp = (__half2*)(g_xh + (size_t)idx * 4);
        hp[0] = __halves2half2(__float2half_rn(v.x), __float2half_rn(v.y));
        hp[1] = __halves2half2(__float2half_rn(v.z), __float2half_rn(v.w));
        return;
    }
    if (idx >= n4w) return;
    float4 v = ((const float4*)wq)[idx];
    __half2 l0, l1;
    __half2 h0 = split_hl(v.x, v.y, l0);
    __half2 h1 = split_hl(v.z, v.w, l1);
    __half2* hp = (__half2*)(g_wqh + (size_t)idx * 4);
    hp[0] = h0; hp[1] = h1;
    __half2* lp = (__half2*)(g_wql + (size_t)idx * 4);
    lp[0] = l0; lp[1] = l1;
}

// Softmax over key axis + differential combine; writes f16 hi+lo scores
__global__ void __launch_bounds__(256)
softmax_combine_kernel(const float* __restrict__ lq1, const float* __restrict__ lk1,
                       const float* __restrict__ lq2, const float* __restrict__ lk2)
{
    const int r = blockIdx.x, b = blockIdx.y;
    const size_t off = ((size_t)b * SEQ + r) * SEQ;
    const float scale = 0.04419417382415922f;  // 1/sqrt(512)
    const int tid = threadIdx.x;
    const int lane = tid & 31, warp = tid >> 5;

    float v1a = g_l1[off + tid]       * scale;
    float v1b = g_l1[off + tid + 256] * scale;
    float v2a = g_l2[off + tid]       * scale;
    float v2b = g_l2[off + tid + 256] * scale;

    __shared__ float red1[8], red2[8];

    float m1 = fmaxf(v1a, v1b), m2 = fmaxf(v2a, v2b);
#pragma unroll
    for (int o = 16; o; o >>= 1) {
        m1 = fmaxf(m1, __shfl_xor_sync(0xffffffffu, m1, o));
        m2 = fmaxf(m2, __shfl_xor_sync(0xffffffffu, m2, o));
    }
    if (lane == 0) { red1[warp] = m1; red2[warp] = m2; }
    __syncthreads();
    m1 = red1[0]; m2 = red2[0];
#pragma unroll
    for (int i = 1; i < 8; i++) { m1 = fmaxf(m1, red1[i]); m2 = fmaxf(m2, red2[i]); }
    __syncthreads();

    float e1a = expf(v1a - m1), e1b = expf(v1b - m1);
    float e2a = expf(v2a - m2), e2b = expf(v2b - m2);
    float s1 = e1a + e1b, s2 = e2a + e2b;
#pragma unroll
    for (int o = 16; o; o >>= 1) {
        s1 += __shfl_xor_sync(0xffffffffu, s1, o);
        s2 += __shfl_xor_sync(0xffffffffu, s2, o);
    }
    if (lane == 0) { red1[warp] = s1; red2[warp] = s2; }
    __syncthreads();
    s1 = 0.f; s2 = 0.f;
#pragma unroll
    for (int i = 0; i < 8; i++) { s1 += red1[i]; s2 += red2[i]; }
    const float inv1 = 1.f / s1, inv2 = 1.f / s2;

#pragma unroll
    for (int half = 0; half < 2; half++) {
        const int k = tid + half * 256;
        float e1 = half ? e1b : e1a;
        float e2 = half ? e2b : e2a;
        float lam = expf(lq1[k] * lk1[k]) - expf(lq2[k] * lk2[k]) + LAMBDA_INIT;
        float v = e1 * inv1 - lam * (e2 * inv2);
        __half hh = __float2half_rn(v);
        g_sch[off + k] = hh;
        g_scl[off + k] = __float2half_rn(v - __half2float(hh));
    }
}

// ---------------------------------------------------------------------------
extern "C" void kernel_launch(void* const* d_in, const int* in_sizes, int n_in,
                              void* d_out, int out_size)
{
    const float* x    = (const float*)d_in[0];
    const float* wq_w = (const float*)d_in[1];
    const float* wq_b = (const float*)d_in[2];
    const float* wk_w = (const float*)d_in[3];
    const float* wk_b = (const float*)d_in[4];
    const float* wv_w = (const float*)d_in[5];
    const float* wv_b = (const float*)d_in[6];
    const float* lq1  = (const float*)d_in[7];
    const float* lk1  = (const float*)d_in[8];
    const float* lq2  = (const float*)d_in[9];
    const float* lk2  = (const float*)d_in[10];
    float* out = (float*)d_out;

    cudaFuncSetAttribute(proj_q_kernel,    cudaFuncAttributeMaxDynamicSharedMemorySize, DSMEM_BYTES_P);
    cudaFuncSetAttribute(proj_k_kernel,    cudaFuncAttributeMaxDynamicSharedMemorySize, DSMEM_BYTES_P);
    cudaFuncSetAttribute(proj_v_kernel,    cudaFuncAttributeMaxDynamicSharedMemorySize, DSMEM_BYTES_P);
    cudaFuncSetAttribute(logits_tr_kernel, cudaFuncAttributeMaxDynamicSharedMemorySize, DSMEM_BYTES_3P);
    cudaFuncSetAttribute(out_gemm_kernel,  cudaFuncAttributeMaxDynamicSharedMemorySize, DSMEM_BYTES_3P);

    const int n4x = 4096 * 4096 / 4;
    const int n4w = TWO_D * 4096 / 4;

    // 0: convert x (hi) + wq (hi/lo)
    conv_xq_kernel<<<dim3(n4w / 256, 1, 2), 256>>>(x, wq_w, n4x, n4w);

    dim3 projGridP(TWO_D / 128, (NB * SEQ) / 128, 2);   // (64, 32, 2): z=1 payload
    dim3 projGrid (TWO_D / 128, (NB * SEQ) / 128, 1);

    proj_q_kernel<<<projGridP, 256, DSMEM_BYTES_P>>>(wq_b, wk_w);   // 1 (+conv wk)
    proj_k_kernel<<<projGridP, 256, DSMEM_BYTES_P>>>(wk_b, wv_w);   // 2 (+conv wv)
    proj_v_kernel<<<projGrid,  256, DSMEM_BYTES_P>>>(wv_b);         // 3 <- profiled

    dim3 logitsGrid(SEQ / 256, SEQ / 128, 16 + 64);     // (2, 4, 80): z>=16 transpose
    logits_tr_kernel<<<logitsGrid, NTHREAD, DSMEM_BYTES_3P>>>();    // 4

    dim3 smGrid(SEQ, NB);
    softmax_combine_kernel<<<smGrid, 256>>>(lq1, lk1, lq2, lk2);    // 5

    dim3 outGrid(TWO_D / 256, SEQ / 128, NB);           // (32, 4, 8)
    out_gemm_kernel<<<outGrid, NTHREAD, DSMEM_BYTES_3P>>>(out);     // 6
}

// round 15
// speedup vs baseline: 1.0825x; 1.0012x over previous
#include <cuda_runtime.h>
#include <cuda_fp16.h>
#include <cstdint>
#include <math.h>

// Problem constants
#define D_MODEL 4096
#define TWO_D   8192
#define NB      8
#define SEQ     512
#define LAMBDA_INIT 0.8f

// ---------------------------------------------------------------------------
// Scratch (static device globals; no runtime allocation allowed)
// ---------------------------------------------------------------------------
__device__ __align__(256) __half g_xh [(size_t)4096 * 4096];
__device__ __align__(256) __half g_wqh[(size_t)TWO_D * 4096];
__device__ __align__(256) __half g_wql[(size_t)TWO_D * 4096];
__device__ __align__(256) __half g_wkh[(size_t)TWO_D * 4096];
__device__ __align__(256) __half g_wkl[(size_t)TWO_D * 4096];
__device__ __align__(256) __half g_wvh[(size_t)TWO_D * 4096];
__device__ __align__(256) __half g_wvl[(size_t)TWO_D * 4096];
__device__ __align__(256) __half g_qh [(size_t)NB * SEQ * TWO_D];
__device__ __align__(256) __half g_ql [(size_t)NB * SEQ * TWO_D];
__device__ __align__(256) __half g_kh [(size_t)NB * SEQ * TWO_D];
__device__ __align__(256) __half g_kl [(size_t)NB * SEQ * TWO_D];
__device__ __align__(256) __half g_vh [(size_t)NB * SEQ * TWO_D];
__device__ __align__(256) __half g_vl [(size_t)NB * SEQ * TWO_D];
__device__ __align__(256) __half g_vth[(size_t)NB * TWO_D * SEQ];
__device__ __align__(256) __half g_vtl[(size_t)NB * TWO_D * SEQ];
__device__ __align__(256) float  g_l1 [(size_t)NB * SEQ * SEQ];
__device__ __align__(256) float  g_l2 [(size_t)NB * SEQ * SEQ];
__device__ __align__(256) __half g_sch[(size_t)NB * SEQ * SEQ];
__device__ __align__(256) __half g_scl[(size_t)NB * SEQ * SEQ];

// ---------------------------------------------------------------------------
// PTX primitives (arch-neutral: sm_80+)
// ---------------------------------------------------------------------------
__device__ __forceinline__ uint32_t smem_u32(const void* p) {
    uint32_t a;
    asm("{ .reg .u64 t; cvta.to.shared.u64 t, %1; cvt.u32.u64 %0, t; }"
        : "=r"(a) : "l"(p));
    return a;
}

__device__ __forceinline__ void cpa16(uint32_t dst, const void* src) {
    asm volatile("cp.async.cg.shared.global [%0], [%1], 16;\n"
                 :: "r"(dst), "l"(src));
}
#define CP_COMMIT() asm volatile("cp.async.commit_group;\n" ::: "memory")
#define CP_WAIT(N)  asm volatile("cp.async.wait_group %0;\n" :: "n"(N) : "memory")

#define LDSM4(R, addr) \
    asm volatile("ldmatrix.sync.aligned.m8n8.x4.shared.b16 {%0,%1,%2,%3}, [%4];" \
        : "=r"((R)[0]), "=r"((R)[1]), "=r"((R)[2]), "=r"((R)[3]) : "r"(addr))

__device__ __forceinline__ void mma_f16(float* c, const uint32_t* a,
                                        uint32_t b0, uint32_t b1) {
    asm volatile(
        "mma.sync.aligned.m16n8k16.row.col.f32.f16.f16.f32 "
        "{%0,%1,%2,%3}, {%4,%5,%6,%7}, {%8,%9}, {%0,%1,%2,%3};"
        : "+f"(c[0]), "+f"(c[1]), "+f"(c[2]), "+f"(c[3])
        : "r"(a[0]), "r"(a[1]), "r"(a[2]), "r"(a[3]), "r"(b0), "r"(b1));
}

// Swizzled smem byte offset: tile row r (64B rows), 16B-granule g
__device__ __forceinline__ uint32_t swz(uint32_t r, uint32_t g) {
    return r * 64u + (((g ^ ((r >> 1) & 3u)) << 4));
}

__device__ __forceinline__ __half2 split_hl(float a, float b, __half2& lo) {
    __half ha = __float2half_rn(a), hb = __float2half_rn(b);
    lo = __halves2half2(__float2half_rn(a - __half2float(ha)),
                        __float2half_rn(b - __half2float(hb)));
    return __halves2half2(ha, hb);
}

// ---------------------------------------------------------------------------
// Projection GEMM: C[128,128] = A[128,K] @ B[128,K]^T, fp16 2-product
// (AhBh + AhBl, A hi-only).  256 threads, 8 warps, warp tile 64x32,
// 4 stages x 24KB -> 2 CTAs/SM.  Writes f16 hi/lo + bias.
// ---------------------------------------------------------------------------
#define BK       32
#define PSTAGE   24576
#define POFF_BH  8192
#define POFF_BL  16384
#define DSMEM_BYTES_P (4 * PSTAGE + 1024)        // 99,328 x2 = 198,656

__device__ __forceinline__ void gemm_body_proj(
    const __half* __restrict__ Ah_, int lda,
    const __half* __restrict__ Bh_, const __half* __restrict__ Bl_, int ldb,
    int K, int ldc,
    __half* __restrict__ Ch, __half* __restrict__ Cl,
    const float* __restrict__ bias)
{
    extern __shared__ char dsm_raw[];
    const uint32_t sb = (smem_u32(dsm_raw) + 1023u) & ~1023u;

    const int tid  = threadIdx.x;
    const int wid  = tid >> 5;
    const int lane = tid & 31;
    const int warp_m = wid & 1;
    const int warp_n = wid >> 1;      // 4 in N (32 cols each)

    float acc[4][4][4];
#pragma unroll
    for (int i = 0; i < 4; i++)
#pragma unroll
        for (int j = 0; j < 4; j++)
#pragma unroll
            for (int q = 0; q < 4; q++) acc[i][j][q] = 0.f;

    const int rA = tid >> 2, gA = tid & 3;
    const uint32_t d0 = swz(rA, gA), d1 = swz(rA + 64, gA);
    const size_t aoff0 = (size_t)rA * lda + gA * 8;
    const size_t aoff1 = (size_t)(rA + 64) * lda + gA * 8;
    const size_t boff0 = (size_t)rA * ldb + gA * 8;
    const size_t boff1 = (size_t)(rA + 64) * ldb + gA * 8;

    auto load_stage = [&](int st, int kidx) {
        const int k0 = kidx * BK;
        const uint32_t sd = sb + st * PSTAGE;
        cpa16(sd + d0, Ah_ + aoff0 + k0);
        cpa16(sd + d1, Ah_ + aoff1 + k0);
        cpa16(sd + POFF_BH + d0, Bh_ + boff0 + k0);
        cpa16(sd + POFF_BH + d1, Bh_ + boff1 + k0);
        cpa16(sd + POFF_BL + d0, Bl_ + boff0 + k0);
        cpa16(sd + POFF_BL + d1, Bl_ + boff1 + k0);
    };

    const int kt = K / BK;
#pragma unroll
    for (int s = 0; s < 3; s++) {
        load_stage(s, s);
        CP_COMMIT();
    }

    const uint32_t a_row = warp_m * 64 + (lane & 7) + (((lane >> 3) & 1) << 3);
    const uint32_t a_gb  = lane >> 4;
    const uint32_t b_row = warp_n * 32 + (lane & 7) + ((lane >> 4) << 3);
    const uint32_t b_gb  = (lane >> 3) & 1;

    for (int it = 0; it < kt; it++) {
        CP_WAIT(2);
        __syncthreads();

        const int nf = it + 3;
        if (nf < kt) load_stage(nf & 3, nf);
        CP_COMMIT();

        const uint32_t st = sb + (it & 3) * PSTAGE;
#pragma unroll
        for (int ks = 0; ks < 2; ks++) {
            const uint32_t ag = ks * 2 + a_gb;
            const uint32_t bg = ks * 2 + b_gb;
            uint32_t ah[4][4];
#pragma unroll
            for (int mt = 0; mt < 4; mt++)
                LDSM4(ah[mt], st + swz(a_row + mt * 16, ag));
            uint32_t bh[2][4], bl[2][4];
#pragma unroll
            for (int nc = 0; nc < 2; nc++) {
                const uint32_t bd = st + swz(b_row + nc * 16, bg);
                LDSM4(bh[nc], bd + POFF_BH);
                LDSM4(bl[nc], bd + POFF_BL);
            }
#pragma unroll
            for (int mt = 0; mt < 4; mt++)
#pragma unroll
                for (int nt = 0; nt < 4; nt++) {
                    const int nc = nt >> 1, h = nt & 1;
                    mma_f16(acc[mt][nt], ah[mt], bh[nc][h * 2], bh[nc][h * 2 + 1]);
                }
#pragma unroll
            for (int mt = 0; mt < 4; mt++)
#pragma unroll
                for (int nt = 0; nt < 4; nt++) {
                    const int nc = nt >> 1, h = nt & 1;
                    mma_f16(acc[mt][nt], ah[mt], bl[nc][h * 2], bl[nc][h * 2 + 1]);
                }
        }
    }

#pragma unroll
    for (int mt = 0; mt < 4; mt++) {
        const int r = warp_m * 64 + mt * 16 + (lane >> 2);
#pragma unroll
        for (int nt = 0; nt < 4; nt++) {
            const int c = warp_n * 32 + nt * 8 + (lane & 3) * 2;
            float2 bb = __ldg((const float2*)(bias + c));
            float v00 = acc[mt][nt][0] + bb.x, v01 = acc[mt][nt][1] + bb.y;
            float v10 = acc[mt][nt][2] + bb.x, v11 = acc[mt][nt][3] + bb.y;
            __half2 l0, l1;
            __half2 h0 = split_hl(v00, v01, l0);
            __half2 h1 = split_hl(v10, v11, l1);
            *(__half2*)(Ch + (size_t)r * ldc + c) = h0;
            *(__half2*)(Ch + (size_t)(r + 8) * ldc + c) = h1;
            *(__half2*)(Cl + (size_t)r * ldc + c) = l0;
            *(__half2*)(Cl + (size_t)(r + 8) * ldc + c) = l1;
        }
    }
}

// ---------------------------------------------------------------------------
// 3-product GEMM (logits/output): C[128,128] = A[128,K] @ B[128,K]^T,
// (AhBh + AhBl + AlBh).  256 threads, warp tile 64x32,
// 3 stages x 32KB = 96KB -> 2 CTAs/SM.  fp32 epilogue.
// ---------------------------------------------------------------------------
#define LSTAGE   32768
#define LOFF_AL  8192
#define LOFF_BH  16384
#define LOFF_BL  24576
#define DSMEM_BYTES_L (3 * LSTAGE + 1024)        // 99,328 x2 = 198,656

__device__ __forceinline__ void gemm_body_3p128(
    const __half* __restrict__ Ah_, const __half* __restrict__ Al_, int lda,
    const __half* __restrict__ Bh_, const __half* __restrict__ Bl_, int ldb,
    int K, float* __restrict__ C, int ldc)
{
    extern __shared__ char dsm_raw[];
    const uint32_t sb = (smem_u32(dsm_raw) + 1023u) & ~1023u;

    const int tid  = threadIdx.x;
    const int wid  = tid >> 5;
    const int lane = tid & 31;
    const int warp_m = wid & 1;
    const int warp_n = wid >> 1;

    float acc[4][4][4];
#pragma unroll
    for (int i = 0; i < 4; i++)
#pragma unroll
        for (int j = 0; j < 4; j++)
#pragma unroll
            for (int q = 0; q < 4; q++) acc[i][j][q] = 0.f;

    const int rA = tid >> 2, gA = tid & 3;
    const uint32_t d0 = swz(rA, gA), d1 = swz(rA + 64, gA);
    const size_t aoff0 = (size_t)rA * lda + gA * 8;
    const size_t aoff1 = (size_t)(rA + 64) * lda + gA * 8;
    const size_t boff0 = (size_t)rA * ldb + gA * 8;
    const size_t boff1 = (size_t)(rA + 64) * ldb + gA * 8;

    auto load_stage = [&](int st, int kidx) {
        const int k0 = kidx * BK;
        const uint32_t sd = sb + st * LSTAGE;
        cpa16(sd + d0, Ah_ + aoff0 + k0);
        cpa16(sd + d1, Ah_ + aoff1 + k0);
        cpa16(sd + LOFF_AL + d0, Al_ + aoff0 + k0);
        cpa16(sd + LOFF_AL + d1, Al_ + aoff1 + k0);
        cpa16(sd + LOFF_BH + d0, Bh_ + boff0 + k0);
        cpa16(sd + LOFF_BH + d1, Bh_ + boff1 + k0);
        cpa16(sd + LOFF_BL + d0, Bl_ + boff0 + k0);
        cpa16(sd + LOFF_BL + d1, Bl_ + boff1 + k0);
    };

    const int kt = K / BK;
#pragma unroll
    for (int s = 0; s < 2; s++) {
        load_stage(s, s);
        CP_COMMIT();
    }

    const uint32_t a_row = warp_m * 64 + (lane & 7) + (((lane >> 3) & 1) << 3);
    const uint32_t a_gb  = lane >> 4;
    const uint32_t b_row = warp_n * 32 + (lane & 7) + ((lane >> 4) << 3);
    const uint32_t b_gb  = (lane >> 3) & 1;

    int slot = 0;
    for (int it = 0; it < kt; it++) {
        CP_WAIT(1);
        __syncthreads();

        const int nf = it + 2;
        if (nf < kt) {
            int ws = slot + 2; if (ws >= 3) ws -= 3;
            load_stage(ws, nf);
        }
        CP_COMMIT();

        const uint32_t st = sb + slot * LSTAGE;
        if (++slot == 3) slot = 0;
#pragma unroll
        for (int ks = 0; ks < 2; ks++) {
            const uint32_t ag = ks * 2 + a_gb;
            const uint32_t bg = ks * 2 + b_gb;
            uint32_t ah[4][4], al[4][4];
#pragma unroll
            for (int mt = 0; mt < 4; mt++) {
                const uint32_t ad = st + swz(a_row + mt * 16, ag);
                LDSM4(ah[mt], ad);
                LDSM4(al[mt], ad + LOFF_AL);
            }
            uint32_t bh[2][4], bl[2][4];
#pragma unroll
            for (int nc = 0; nc < 2; nc++) {
                const uint32_t bd = st + swz(b_row + nc * 16, bg);
                LDSM4(bh[nc], bd + LOFF_BH);
                LDSM4(bl[nc], bd + LOFF_BL);
            }
#pragma unroll
            for (int mt = 0; mt < 4; mt++)
#pragma unroll
                for (int nt = 0; nt < 4; nt++) {
                    const int nc = nt >> 1, h = nt & 1;
                    mma_f16(acc[mt][nt], ah[mt], bh[nc][h * 2], bh[nc][h * 2 + 1]);
                }
#pragma unroll
            for (int mt = 0; mt < 4; mt++)
#pragma unroll
                for (int nt = 0; nt < 4; nt++) {
                    const int nc = nt >> 1, h = nt & 1;
                    mma_f16(acc[mt][nt], ah[mt], bl[nc][h * 2], bl[nc][h * 2 + 1]);
                }
#pragma unroll
            for (int mt = 0; mt < 4; mt++)
#pragma unroll
                for (int nt = 0; nt < 4; nt++) {
                    const int nc = nt >> 1, h = nt & 1;
                    mma_f16(acc[mt][nt], al[mt], bh[nc][h * 2], bh[nc][h * 2 + 1]);
                }
        }
    }

#pragma unroll
    for (int mt = 0; mt < 4; mt++) {
        const int r = warp_m * 64 + mt * 16 + (lane >> 2);
#pragma unroll
        for (int nt = 0; nt < 4; nt++) {
            const int c = warp_n * 32 + nt * 8 + (lane & 3) * 2;
            float2 s;
            s.x = acc[mt][nt][0]; s.y = acc[mt][nt][1];
            *(float2*)(C + (size_t)r * ldc + c) = s;
            s.x = acc[mt][nt][2]; s.y = acc[mt][nt][3];
            *(float2*)(C + (size_t)(r + 8) * ldc + c) = s;
        }
    }
}

// Supertile remap for L2 reuse (G must divide gridDim.y)
__device__ __forceinline__ void remap_xy(int G, int& bx, int& by) {
    int lin = blockIdx.y * gridDim.x + blockIdx.x;
    int per = G * gridDim.x;
    int grp = lin / per, rem = lin % per;
    by = grp * G + (rem % G);
    bx = rem / G;
}

// ---------------------------------------------------------------------------
// Conversion payload (z=1 slab of proj launches): full weight hi/lo split
// ---------------------------------------------------------------------------
__device__ __forceinline__ void conv_w_block(const float* __restrict__ src,
                                             __half* __restrict__ h,
                                             __half* __restrict__ l)
{
    const int nblk = gridDim.x * gridDim.y;
    const int per = (TWO_D * 4096 / 4) / nblk;
    const int blin = blockIdx.y * gridDim.x + blockIdx.x;
    const size_t base = (size_t)blin * per;
    const float4* s4 = (const float4*)src;
    for (int i = threadIdx.x; i < per; i += blockDim.x) {
        const size_t idx = base + i;
        float4 v = s4[idx];
        __half2 l0, l1;
        __half2 h0 = split_hl(v.x, v.y, l0);
        __half2 h1 = split_hl(v.z, v.w, l1);
        __half2* hp = (__half2*)(h + idx * 4);
        hp[0] = h0; hp[1] = h1;
        __half2* lp = (__half2*)(l + idx * 4);
        lp[0] = l0; lp[1] = l1;
    }
}

// ---------------------------------------------------------------------------
// Projection kernels: 128x128, 256 threads, 2 CTAs/SM (+conv payload z=1)
// ---------------------------------------------------------------------------
__global__ void __launch_bounds__(256, 2)
proj_q_kernel(const float* __restrict__ bias, const float* __restrict__ wk_src)
{
    if (blockIdx.z == 1) { conv_w_block(wk_src, g_wkh, g_wkl); return; }
    int bx, by; remap_xy(8, bx, by);
    const int tm = by * 128, tn = bx * 128;
    gemm_body_proj(g_xh + (size_t)tm * D_MODEL, D_MODEL,
                   g_wqh + (size_t)tn * D_MODEL, g_wql + (size_t)tn * D_MODEL, D_MODEL,
                   D_MODEL, TWO_D,
                   g_qh + (size_t)tm * TWO_D + tn, g_ql + (size_t)tm * TWO_D + tn,
                   bias + tn);
}

__global__ void __launch_bounds__(256, 2)
proj_k_kernel(const float* __restrict__ bias, const float* __restrict__ wv_src)
{
    if (blockIdx.z == 1) { conv_w_block(wv_src, g_wvh, g_wvl); return; }
    int bx, by; remap_xy(8, bx, by);
    const int tm = by * 128, tn = bx * 128;
    gemm_body_proj(g_xh + (size_t)tm * D_MODEL, D_MODEL,
                   g_wkh + (size_t)tn * D_MODEL, g_wkl + (size_t)tn * D_MODEL, D_MODEL,
                   D_MODEL, TWO_D,
                   g_kh + (size_t)tm * TWO_D + tn, g_kl + (size_t)tm * TWO_D + tn,
                   bias + tn);
}

__global__ void __launch_bounds__(256, 2)
proj_v_kernel(const float* __restrict__ bias)
{
    int bx, by; remap_xy(8, bx, by);
    const int tm = by * 128, tn = bx * 128;
    gemm_body_proj(g_xh + (size_t)tm * D_MODEL, D_MODEL,
                   g_wvh + (size_t)tn * D_MODEL, g_wvl + (size_t)tn * D_MODEL, D_MODEL,
                   D_MODEL, TWO_D,
                   g_vh + (size_t)tm * TWO_D + tn, g_vl + (size_t)tm * TWO_D + tn,
                   bias + tn);
}

// ---------------------------------------------------------------------------
// Logits (128x128, 2 CTAs/SM) + V-transpose payload (z >= 16).
// grid (4, 4, 16+16): z<16 -> logits tile, z>=16 -> 256 transpose blocks.
// ---------------------------------------------------------------------------
__global__ void __launch_bounds__(256, 2)
logits_tr_kernel()
{
    if (blockIdx.z >= 16) {
        extern __shared__ char dsm_raw[];
        const int blin = (blockIdx.z - 16) * 16 + blockIdx.y * 4 + blockIdx.x; // 0..255
        const int tx = threadIdx.x & 31, ty = threadIdx.x >> 5;  // 32 x 8
        __half (*th)[34] = (__half(*)[34])(dsm_raw);
        __half (*tl)[34] = (__half(*)[34])(dsm_raw + 2304);
        for (int job = blin; job < 32768; job += 256) {
            const int nx = job & 255;                     // TWO_D/32
            const int sy = (job >> 8) & 15;               // SEQ/32
            const int b  = job >> 12;                     // NB
            const size_t sbase = (size_t)b * SEQ * TWO_D;
            const int s0 = sy * 32, n0 = nx * 32;
#pragma unroll
            for (int i = ty; i < 32; i += 8) {
                size_t o = sbase + (size_t)(s0 + i) * TWO_D + n0 + tx;
                th[i][tx] = g_vh[o];
                tl[i][tx] = g_vl[o];
            }
            __syncthreads();
            const size_t dbase = (size_t)b * TWO_D * SEQ;
#pragma unroll
            for (int i = ty; i < 32; i += 8) {
                size_t o = dbase + (size_t)(n0 + i) * SEQ + s0 + tx;
                g_vth[o] = th[tx][i];
                g_vtl[o] = tl[tx][i];
            }
            __syncthreads();
        }
        return;
    }
    const int bz = blockIdx.z;
    const int b = bz >> 1, pair = bz & 1;
    const int tm = blockIdx.y * 128, tn = blockIdx.x * 128;
    const size_t qoff = (size_t)b * SEQ * TWO_D + (size_t)pair * D_MODEL;
    float* C = (pair ? g_l2 : g_l1) + (size_t)b * SEQ * SEQ
             + (size_t)tm * SEQ + tn;
    gemm_body_3p128(g_qh + qoff + (size_t)tm * TWO_D,
                    g_ql + qoff + (size_t)tm * TWO_D, TWO_D,
                    g_kh + qoff + (size_t)tn * TWO_D,
                    g_kl + qoff + (size_t)tn * TWO_D, TWO_D,
                    D_MODEL, C, SEQ);
}

// Output GEMM: 128x128, 2 CTAs/SM.  grid (64, 4, 8).
__global__ void __launch_bounds__(256, 2)
out_gemm_kernel(float* __restrict__ out)
{
    const int b = blockIdx.z;
    int bx, by; remap_xy(4, bx, by);
    const int tm = by * 128, tn = bx * 128;
    const size_t soff = (size_t)b * SEQ * SEQ + (size_t)tm * SEQ;
    const size_t voff = (size_t)b * TWO_D * SEQ + (size_t)tn * SEQ;
    gemm_body_3p128(g_sch + soff, g_scl + soff, SEQ,
                    g_vth + voff, g_vtl + voff, SEQ,
                    SEQ, out + (size_t)b * SEQ * TWO_D + (size_t)tm * TWO_D + tn, TWO_D);
}

// ---------------------------------------------------------------------------
// Support kernels
// ---------------------------------------------------------------------------
__global__ void __launch_bounds__(256)
conv_xq_kernel(const float* __restrict__ x, const float* __restrict__ wq,
               int n4x, int n4w)
{
    const int idx = blockIdx.x * 256 + threadIdx.x;
    if (blockIdx.z == 0) {
        if (idx >= n4x) return;
        float4 v = ((const float4*)x)[idx];
        __half2* hp = (__half2*)(g_xh + (size_t)idx * 4);
        hp[0] = __halves2half2(__float2half_rn(v.x), __float2half_rn(v.y));
        hp[1] = __halves2half2(__float2half_rn(v.z), __float2half_rn(v.w));
        return;
    }
    if (idx >= n4w) return;
    float4 v = ((const float4*)wq)[idx];
    __half2 l0, l1;
    __half2 h0 = split_hl(v.x, v.y, l0);
    __half2 h1 = split_hl(v.z, v.w, l1);
    __half2* hp = (__half2*)(g_wqh + (size_t)idx * 4);
    hp[0] = h0; hp[1] = h1;
    __half2* lp = (__half2*)(g_wql + (size_t)idx * 4);
    lp[0] = l0; lp[1] = l1;
}

// Softmax over key axis + differential combine; writes f16 hi+lo scores
__global__ void __launch_bounds__(256)
softmax_combine_kernel(const float* __restrict__ lq1, const float* __restrict__ lk1,
                       const float* __restrict__ lq2, const float* __restrict__ lk2)
{
    const int r = blockIdx.x, b = blockIdx.y;
    const size_t off = ((size_t)b * SEQ + r) * SEQ;
    const float scale = 0.04419417382415922f;  // 1/sqrt(512)
    const int tid = threadIdx.x;
    const int lane = tid & 31, warp = tid >> 5;

    float v1a = g_l1[off + tid]       * scale;
    float v1b = g_l1[off + tid + 256] * scale;
    float v2a = g_l2[off + tid]       * scale;
    float v2b = g_l2[off + tid + 256] * scale;

    __shared__ float red1[8], red2[8];

    float m1 = fmaxf(v1a, v1b), m2 = fmaxf(v2a, v2b);
#pragma unroll
    for (int o = 16; o; o >>= 1) {
        m1 = fmaxf(m1, __shfl_xor_sync(0xffffffffu, m1, o));
        m2 = fmaxf(m2, __shfl_xor_sync(0xffffffffu, m2, o));
    }
    if (lane == 0) { red1[warp] = m1; red2[warp] = m2; }
    __syncthreads();
    m1 = red1[0]; m2 = red2[0];
#pragma unroll
    for (int i = 1; i < 8; i++) { m1 = fmaxf(m1, red1[i]); m2 = fmaxf(m2, red2[i]); }
    __syncthreads();

    float e1a = expf(v1a - m1), e1b = expf(v1b - m1);
    float e2a = expf(v2a - m2), e2b = expf(v2b - m2);
    float s1 = e1a + e1b, s2 = e2a + e2b;
#pragma unroll
    for (int o = 16; o; o >>= 1) {
        s1 += __shfl_xor_sync(0xffffffffu, s1, o);
        s2 += __shfl_xor_sync(0xffffffffu, s2, o);
    }
    if (lane == 0) { red1[warp] = s1; red2[warp] = s2; }
    __syncthreads();
    s1 = 0.f; s2 = 0.f;
#pragma unroll
    for (int i = 0; i < 8; i++) { s1 += red1[i]; s2 += red2[i]; }
    const float inv1 = 1.f / s1, inv2 = 1.f / s2;

#pragma unroll
    for (int half = 0; half < 2; half++) {
        const int k = tid + half * 256;
        float e1 = half ? e1b : e1a;
        float e2 = half ? e2b : e2a;
        float lam = expf(lq1[k] * lk1[k]) - expf(lq2[k] * lk2[k]) + LAMBDA_INIT;
        float v = e1 * inv1 - lam * (e2 * inv2);
        __half hh = __float2half_rn(v);
        g_sch[off + k] = hh;
        g_scl[off + k] = __float2half_rn(v - __half2float(hh));
    }
}

// ---------------------------------------------------------------------------
extern "C" void kernel_launch(void* const* d_in, const int* in_sizes, int n_in,
                              void* d_out, int out_size)
{
    const float* x    = (const float*)d_in[0];
    const float* wq_w = (const float*)d_in[1];
    const float* wq_b = (const float*)d_in[2];
    const float* wk_w = (const float*)d_in[3];
    const float* wk_b = (const float*)d_in[4];
    const float* wv_w = (const float*)d_in[5];
    const float* wv_b = (const float*)d_in[6];
    const float* lq1  = (const float*)d_in[7];
    const float* lk1  = (const float*)d_in[8];
    const float* lq2  = (const float*)d_in[9];
    const float* lk2  = (const float*)d_in[10];
    float* out = (float*)d_out;

    cudaFuncSetAttribute(proj_q_kernel,    cudaFuncAttributeMaxDynamicSharedMemorySize, DSMEM_BYTES_P);
    cudaFuncSetAttribute(proj_k_kernel,    cudaFuncAttributeMaxDynamicSharedMemorySize, DSMEM_BYTES_P);
    cudaFuncSetAttribute(proj_v_kernel,    cudaFuncAttributeMaxDynamicSharedMemorySize, DSMEM_BYTES_P);
    cudaFuncSetAttribute(logits_tr_kernel, cudaFuncAttributeMaxDynamicSharedMemorySize, DSMEM_BYTES_L);
    cudaFuncSetAttribute(out_gemm_kernel,  cudaFuncAttributeMaxDynamicSharedMemorySize, DSMEM_BYTES_L);

    const int n4x = 4096 * 4096 / 4;
    const int n4w = TWO_D * 4096 / 4;

    // 0: convert x (hi) + wq (hi/lo)
    conv_xq_kernel<<<dim3(n4w / 256, 1, 2), 256>>>(x, wq_w, n4x, n4w);

    dim3 projGridP(TWO_D / 128, (NB * SEQ) / 128, 2);   // (64, 32, 2): z=1 payload
    dim3 projGrid (TWO_D / 128, (NB * SEQ) / 128, 1);

    proj_q_kernel<<<projGridP, 256, DSMEM_BYTES_P>>>(wq_b, wk_w);   // 1 (+conv wk)
    proj_k_kernel<<<projGridP, 256, DSMEM_BYTES_P>>>(wk_b, wv_w);   // 2 (+conv wv)
    proj_v_kernel<<<projGrid,  256, DSMEM_BYTES_P>>>(wv_b);         // 3 <- profiled

    dim3 logitsGrid(SEQ / 128, SEQ / 128, 16 + 16);     // (4, 4, 32): z>=16 transpose
    logits_tr_kernel<<<logitsGrid, 256, DSMEM_BYTES_L>>>();         // 4

    dim3 smGrid(SEQ, NB);
    softmax_combine_kernel<<<smGrid, 256>>>(lq1, lk1, lq2, lk2);    // 5

    dim3 outGrid(TWO_D / 128, SEQ / 128, NB);           // (64, 4, 8)
    out_gemm_kernel<<<outGrid, 256, DSMEM_BYTES_L>>>(out);          // 6
}

// round 16
// speedup vs baseline: 1.1077x; 1.0233x over previous
#include <cuda_runtime.h>
#include <cuda_fp16.h>
#include <cstdint>
#include <math.h>

// Problem constants
#define D_MODEL 4096
#define TWO_D   8192
#define NB      8
#define SEQ     512
#define LAMBDA_INIT 0.8f

// ---------------------------------------------------------------------------
// Scratch (static device globals; no runtime allocation allowed)
// ---------------------------------------------------------------------------
__device__ __align__(256) __half g_xh [(size_t)4096 * 4096];
__device__ __align__(256) __half g_wqh[(size_t)TWO_D * 4096];
__device__ __align__(256) __half g_wql[(size_t)TWO_D * 4096];
__device__ __align__(256) __half g_wkh[(size_t)TWO_D * 4096];
__device__ __align__(256) __half g_wkl[(size_t)TWO_D * 4096];
__device__ __align__(256) __half g_wvh[(size_t)TWO_D * 4096];
__device__ __align__(256) __half g_wvl[(size_t)TWO_D * 4096];
__device__ __align__(256) __half g_qh [(size_t)NB * SEQ * TWO_D];
__device__ __align__(256) __half g_ql [(size_t)NB * SEQ * TWO_D];
__device__ __align__(256) __half g_kh [(size_t)NB * SEQ * TWO_D];
__device__ __align__(256) __half g_kl [(size_t)NB * SEQ * TWO_D];
__device__ __align__(256) __half g_vh [(size_t)NB * SEQ * TWO_D];
__device__ __align__(256) __half g_vl [(size_t)NB * SEQ * TWO_D];
__device__ __align__(256) __half g_vth[(size_t)NB * TWO_D * SEQ];
__device__ __align__(256) __half g_vtl[(size_t)NB * TWO_D * SEQ];
__device__ __align__(256) float  g_l1 [(size_t)NB * SEQ * SEQ];
__device__ __align__(256) float  g_l2 [(size_t)NB * SEQ * SEQ];
__device__ __align__(256) __half g_sch[(size_t)NB * SEQ * SEQ];
__device__ __align__(256) __half g_scl[(size_t)NB * SEQ * SEQ];

// ---------------------------------------------------------------------------
// PTX primitives (arch-neutral: sm_80+)
// ---------------------------------------------------------------------------
__device__ __forceinline__ uint32_t smem_u32(const void* p) {
    uint32_t a;
    asm("{ .reg .u64 t; cvta.to.shared.u64 t, %1; cvt.u32.u64 %0, t; }"
        : "=r"(a) : "l"(p));
    return a;
}

__device__ __forceinline__ void cpa16(uint32_t dst, const void* src) {
    asm volatile("cp.async.cg.shared.global [%0], [%1], 16;\n"
                 :: "r"(dst), "l"(src));
}
#define CP_COMMIT() asm volatile("cp.async.commit_group;\n" ::: "memory")
#define CP_WAIT(N)  asm volatile("cp.async.wait_group %0;\n" :: "n"(N) : "memory")

#define LDSM4(R, addr) \
    asm volatile("ldmatrix.sync.aligned.m8n8.x4.shared.b16 {%0,%1,%2,%3}, [%4];" \
        : "=r"((R)[0]), "=r"((R)[1]), "=r"((R)[2]), "=r"((R)[3]) : "r"(addr))

__device__ __forceinline__ void mma_f16(float* c, const uint32_t* a,
                                        uint32_t b0, uint32_t b1) {
    asm volatile(
        "mma.sync.aligned.m16n8k16.row.col.f32.f16.f16.f32 "
        "{%0,%1,%2,%3}, {%4,%5,%6,%7}, {%8,%9}, {%0,%1,%2,%3};"
        : "+f"(c[0]), "+f"(c[1]), "+f"(c[2]), "+f"(c[3])
        : "r"(a[0]), "r"(a[1]), "r"(a[2]), "r"(a[3]), "r"(b0), "r"(b1));
}

// Swizzled smem byte offset: tile row r (64B rows), 16B-granule g
__device__ __forceinline__ uint32_t swz(uint32_t r, uint32_t g) {
    return r * 64u + (((g ^ ((r >> 1) & 3u)) << 4));
}

__device__ __forceinline__ __half2 split_hl(float a, float b, __half2& lo) {
    __half ha = __float2half_rn(a), hb = __float2half_rn(b);
    lo = __halves2half2(__float2half_rn(a - __half2float(ha)),
                        __float2half_rn(b - __half2float(hb)));
    return __halves2half2(ha, hb);
}

// ---------------------------------------------------------------------------
// Projection GEMM: C[128,128] = A[128,K] @ B[128,K]^T, fp16 2-product
// (AhBh + AhBl, A hi-only).  256 threads, 8 warps, warp tile 64x32,
// 4 stages x 24KB -> 2 CTAs/SM.  Writes f16 hi/lo + bias.
// ---------------------------------------------------------------------------
#define BK       32
#define PSTAGE   24576
#define POFF_BH  8192
#define POFF_BL  16384
#define DSMEM_BYTES_P (4 * PSTAGE + 1024)        // 99,328 x2 = 198,656

__device__ __forceinline__ void gemm_body_proj(
    const __half* __restrict__ Ah_, int lda,
    const __half* __restrict__ Bh_, const __half* __restrict__ Bl_, int ldb,
    int K, int ldc,
    __half* __restrict__ Ch, __half* __restrict__ Cl,
    const float* __restrict__ bias)
{
    extern __shared__ char dsm_raw[];
    const uint32_t sb = (smem_u32(dsm_raw) + 1023u) & ~1023u;

    const int tid  = threadIdx.x;
    const int wid  = tid >> 5;
    const int lane = tid & 31;
    const int warp_m = wid & 1;
    const int warp_n = wid >> 1;      // 4 in N (32 cols each)

    float acc[4][4][4];
#pragma unroll
    for (int i = 0; i < 4; i++)
#pragma unroll
        for (int j = 0; j < 4; j++)
#pragma unroll
            for (int q = 0; q < 4; q++) acc[i][j][q] = 0.f;

    const int rA = tid >> 2, gA = tid & 3;
    const uint32_t d0 = swz(rA, gA), d1 = swz(rA + 64, gA);
    const size_t aoff0 = (size_t)rA * lda + gA * 8;
    const size_t aoff1 = (size_t)(rA + 64) * lda + gA * 8;
    const size_t boff0 = (size_t)rA * ldb + gA * 8;
    const size_t boff1 = (size_t)(rA + 64) * ldb + gA * 8;

    auto load_stage = [&](int st, int kidx) {
        const int k0 = kidx * BK;
        const uint32_t sd = sb + st * PSTAGE;
        cpa16(sd + d0, Ah_ + aoff0 + k0);
        cpa16(sd + d1, Ah_ + aoff1 + k0);
        cpa16(sd + POFF_BH + d0, Bh_ + boff0 + k0);
        cpa16(sd + POFF_BH + d1, Bh_ + boff1 + k0);
        cpa16(sd + POFF_BL + d0, Bl_ + boff0 + k0);
        cpa16(sd + POFF_BL + d1, Bl_ + boff1 + k0);
    };

    const int kt = K / BK;
#pragma unroll
    for (int s = 0; s < 3; s++) {
        load_stage(s, s);
        CP_COMMIT();
    }

    const uint32_t a_row = warp_m * 64 + (lane & 7) + (((lane >> 3) & 1) << 3);
    const uint32_t a_gb  = lane >> 4;
    const uint32_t b_row = warp_n * 32 + (lane & 7) + ((lane >> 4) << 3);
    const uint32_t b_gb  = (lane >> 3) & 1;

    for (int it = 0; it < kt; it++) {
        CP_WAIT(2);
        __syncthreads();

        const int nf = it + 3;
        if (nf < kt) load_stage(nf & 3, nf);
        CP_COMMIT();

        const uint32_t st = sb + (it & 3) * PSTAGE;
#pragma unroll
        for (int ks = 0; ks < 2; ks++) {
            const uint32_t ag = ks * 2 + a_gb;
            const uint32_t bg = ks * 2 + b_gb;
            uint32_t ah[4][4];
#pragma unroll
            for (int mt = 0; mt < 4; mt++)
                LDSM4(ah[mt], st + swz(a_row + mt * 16, ag));
            uint32_t bh[2][4], bl[2][4];
#pragma unroll
            for (int nc = 0; nc < 2; nc++) {
                const uint32_t bd = st + swz(b_row + nc * 16, bg);
                LDSM4(bh[nc], bd + POFF_BH);
                LDSM4(bl[nc], bd + POFF_BL);
            }
#pragma unroll
            for (int mt = 0; mt < 4; mt++)
#pragma unroll
                for (int nt = 0; nt < 4; nt++) {
                    const int nc = nt >> 1, h = nt & 1;
                    mma_f16(acc[mt][nt], ah[mt], bh[nc][h * 2], bh[nc][h * 2 + 1]);
                }
#pragma unroll
            for (int mt = 0; mt < 4; mt++)
#pragma unroll
                for (int nt = 0; nt < 4; nt++) {
                    const int nc = nt >> 1, h = nt & 1;
                    mma_f16(acc[mt][nt], ah[mt], bl[nc][h * 2], bl[nc][h * 2 + 1]);
                }
        }
    }

#pragma unroll
    for (int mt = 0; mt < 4; mt++) {
        const int r = warp_m * 64 + mt * 16 + (lane >> 2);
#pragma unroll
        for (int nt = 0; nt < 4; nt++) {
            const int c = warp_n * 32 + nt * 8 + (lane & 3) * 2;
            float2 bb = __ldg((const float2*)(bias + c));
            float v00 = acc[mt][nt][0] + bb.x, v01 = acc[mt][nt][1] + bb.y;
            float v10 = acc[mt][nt][2] + bb.x, v11 = acc[mt][nt][3] + bb.y;
            __half2 l0, l1;
            __half2 h0 = split_hl(v00, v01, l0);
            __half2 h1 = split_hl(v10, v11, l1);
            *(__half2*)(Ch + (size_t)r * ldc + c) = h0;
            *(__half2*)(Ch + (size_t)(r + 8) * ldc + c) = h1;
            *(__half2*)(Cl + (size_t)r * ldc + c) = l0;
            *(__half2*)(Cl + (size_t)(r + 8) * ldc + c) = l1;
        }
    }
}

// ---------------------------------------------------------------------------
// 3-product GEMM (logits/output): C[128,128] = A[128,K] @ B[128,K]^T,
// (AhBh + AhBl + AlBh).  256 threads, warp tile 64x32,
// 3 stages x 32KB = 96KB -> 2 CTAs/SM.  fp32 epilogue.
// ---------------------------------------------------------------------------
#define LSTAGE   32768
#define LOFF_AL  8192
#define LOFF_BH  16384
#define LOFF_BL  24576
#define DSMEM_BYTES_L (3 * LSTAGE + 1024)        // 99,328 x2 = 198,656

__device__ __forceinline__ void gemm_body_3p128(
    const __half* __restrict__ Ah_, const __half* __restrict__ Al_, int lda,
    const __half* __restrict__ Bh_, const __half* __restrict__ Bl_, int ldb,
    int K, float* __restrict__ C, int ldc)
{
    extern __shared__ char dsm_raw[];
    const uint32_t sb = (smem_u32(dsm_raw) + 1023u) & ~1023u;

    const int tid  = threadIdx.x;
    const int wid  = tid >> 5;
    const int lane = tid & 31;
    const int warp_m = wid & 1;
    const int warp_n = wid >> 1;

    float acc[4][4][4];
#pragma unroll
    for (int i = 0; i < 4; i++)
#pragma unroll
        for (int j = 0; j < 4; j++)
#pragma unroll
            for (int q = 0; q < 4; q++) acc[i][j][q] = 0.f;

    const int rA = tid >> 2, gA = tid & 3;
    const uint32_t d0 = swz(rA, gA), d1 = swz(rA + 64, gA);
    const size_t aoff0 = (size_t)rA * lda + gA * 8;
    const size_t aoff1 = (size_t)(rA + 64) * lda + gA * 8;
    const size_t boff0 = (size_t)rA * ldb + gA * 8;
    const size_t boff1 = (size_t)(rA + 64) * ldb + gA * 8;

    auto load_stage = [&](int st, int kidx) {
        const int k0 = kidx * BK;
        const uint32_t sd = sb + st * LSTAGE;
        cpa16(sd + d0, Ah_ + aoff0 + k0);
        cpa16(sd + d1, Ah_ + aoff1 + k0);
        cpa16(sd + LOFF_AL + d0, Al_ + aoff0 + k0);
        cpa16(sd + LOFF_AL + d1, Al_ + aoff1 + k0);
        cpa16(sd + LOFF_BH + d0, Bh_ + boff0 + k0);
        cpa16(sd + LOFF_BH + d1, Bh_ + boff1 + k0);
        cpa16(sd + LOFF_BL + d0, Bl_ + boff0 + k0);
        cpa16(sd + LOFF_BL + d1, Bl_ + boff1 + k0);
    };

    const int kt = K / BK;
#pragma unroll
    for (int s = 0; s < 2; s++) {
        load_stage(s, s);
        CP_COMMIT();
    }

    const uint32_t a_row = warp_m * 64 + (lane & 7) + (((lane >> 3) & 1) << 3);
    const uint32_t a_gb  = lane >> 4;
    const uint32_t b_row = warp_n * 32 + (lane & 7) + ((lane >> 4) << 3);
    const uint32_t b_gb  = (lane >> 3) & 1;

    int slot = 0;
    for (int it = 0; it < kt; it++) {
        CP_WAIT(1);
        __syncthreads();

        const int nf = it + 2;
        if (nf < kt) {
            int ws = slot + 2; if (ws >= 3) ws -= 3;
            load_stage(ws, nf);
        }
        CP_COMMIT();

        const uint32_t st = sb + slot * LSTAGE;
        if (++slot == 3) slot = 0;
#pragma unroll
        for (int ks = 0; ks < 2; ks++) {
            const uint32_t ag = ks * 2 + a_gb;
            const uint32_t bg = ks * 2 + b_gb;
            uint32_t ah[4][4], al[4][4];
#pragma unroll
            for (int mt = 0; mt < 4; mt++) {
                const uint32_t ad = st + swz(a_row + mt * 16, ag);
                LDSM4(ah[mt], ad);
                LDSM4(al[mt], ad + LOFF_AL);
            }
            uint32_t bh[2][4], bl[2][4];
#pragma unroll
            for (int nc = 0; nc < 2; nc++) {
                const uint32_t bd = st + swz(b_row + nc * 16, bg);
                LDSM4(bh[nc], bd + LOFF_BH);
                LDSM4(bl[nc], bd + LOFF_BL);
            }
#pragma unroll
            for (int mt = 0; mt < 4; mt++)
#pragma unroll
                for (int nt = 0; nt < 4; nt++) {
                    const int nc = nt >> 1, h = nt & 1;
                    mma_f16(acc[mt][nt], ah[mt], bh[nc][h * 2], bh[nc][h * 2 + 1]);
                }
#pragma unroll
            for (int mt = 0; mt < 4; mt++)
#pragma unroll
                for (int nt = 0; nt < 4; nt++) {
                    const int nc = nt >> 1, h = nt & 1;
                    mma_f16(acc[mt][nt], ah[mt], bl[nc][h * 2], bl[nc][h * 2 + 1]);
                }
#pragma unroll
            for (int mt = 0; mt < 4; mt++)
#pragma unroll
                for (int nt = 0; nt < 4; nt++) {
                    const int nc = nt >> 1, h = nt & 1;
                    mma_f16(acc[mt][nt], al[mt], bh[nc][h * 2], bh[nc][h * 2 + 1]);
                }
        }
    }

#pragma unroll
    for (int mt = 0; mt < 4; mt++) {
        const int r = warp_m * 64 + mt * 16 + (lane >> 2);
#pragma unroll
        for (int nt = 0; nt < 4; nt++) {
            const int c = warp_n * 32 + nt * 8 + (lane & 3) * 2;
            float2 s;
            s.x = acc[mt][nt][0]; s.y = acc[mt][nt][1];
            *(float2*)(C + (size_t)r * ldc + c) = s;
            s.x = acc[mt][nt][2]; s.y = acc[mt][nt][3];
            *(float2*)(C + (size_t)(r + 8) * ldc + c) = s;
        }
    }
}

// Supertile remap for L2 reuse (G must divide gridDim.y)
__device__ __forceinline__ void remap_xy(int G, int& bx, int& by) {
    int lin = blockIdx.y * gridDim.x + blockIdx.x;
    int per = G * gridDim.x;
    int grp = lin / per, rem = lin % per;
    by = grp * G + (rem % G);
    bx = rem / G;
}

// ---------------------------------------------------------------------------
// Conversion payload (z-slab of proj_q launch): full weight hi/lo split.
// nblk blocks cover (TWO_D*4096/4) float4s.
// ---------------------------------------------------------------------------
__device__ __forceinline__ void conv_w_block(const float* __restrict__ src,
                                             __half* __restrict__ h,
                                             __half* __restrict__ l)
{
    const int nblk = gridDim.x * gridDim.y;
    const int per = (TWO_D * 4096 / 4) / nblk;
    const int blin = blockIdx.y * gridDim.x + blockIdx.x;
    const size_t base = (size_t)blin * per;
    const float4* s4 = (const float4*)src;
    for (int i = threadIdx.x; i < per; i += blockDim.x) {
        const size_t idx = base + i;
        float4 v = s4[idx];
        __half2 l0, l1;
        __half2 h0 = split_hl(v.x, v.y, l0);
        __half2 h1 = split_hl(v.z, v.w, l1);
        __half2* hp = (__half2*)(h + idx * 4);
        hp[0] = h0; hp[1] = h1;
        __half2* lp = (__half2*)(l + idx * 4);
        lp[0] = l0; lp[1] = l1;
    }
}

// ---------------------------------------------------------------------------
// proj_q: GEMM (z=0) + conv wk (z=1) + conv wv (z=2).
// ---------------------------------------------------------------------------
__global__ void __launch_bounds__(256, 2)
proj_q_kernel(const float* __restrict__ bias,
              const float* __restrict__ wk_src, const float* __restrict__ wv_src)
{
    if (blockIdx.z == 1) { conv_w_block(wk_src, g_wkh, g_wkl); return; }
    if (blockIdx.z == 2) { conv_w_block(wv_src, g_wvh, g_wvl); return; }
    int bx, by; remap_xy(8, bx, by);
    const int tm = by * 128, tn = bx * 128;
    gemm_body_proj(g_xh + (size_t)tm * D_MODEL, D_MODEL,
                   g_wqh + (size_t)tn * D_MODEL, g_wql + (size_t)tn * D_MODEL, D_MODEL,
                   D_MODEL, TWO_D,
                   g_qh + (size_t)tm * TWO_D + tn, g_ql + (size_t)tm * TWO_D + tn,
                   bias + tn);
}

// ---------------------------------------------------------------------------
// proj_kv: K projection (z=0) and V projection (z=1) merged in ONE launch —
// no inter-kernel drain between them; tails interleave.
// ---------------------------------------------------------------------------
__global__ void __launch_bounds__(256, 2)
proj_kv_kernel(const float* __restrict__ bias_k, const float* __restrict__ bias_v)
{
    int bx, by; remap_xy(8, bx, by);
    const int tm = by * 128, tn = bx * 128;
    if (blockIdx.z == 0) {
        gemm_body_proj(g_xh + (size_t)tm * D_MODEL, D_MODEL,
                       g_wkh + (size_t)tn * D_MODEL, g_wkl + (size_t)tn * D_MODEL, D_MODEL,
                       D_MODEL, TWO_D,
                       g_kh + (size_t)tm * TWO_D + tn, g_kl + (size_t)tm * TWO_D + tn,
                       bias_k + tn);
    } else {
        gemm_body_proj(g_xh + (size_t)tm * D_MODEL, D_MODEL,
                       g_wvh + (size_t)tn * D_MODEL, g_wvl + (size_t)tn * D_MODEL, D_MODEL,
                       D_MODEL, TWO_D,
                       g_vh + (size_t)tm * TWO_D + tn, g_vl + (size_t)tm * TWO_D + tn,
                       bias_v + tn);
    }
}

// ---------------------------------------------------------------------------
// Logits (128x128, 2 CTAs/SM) + V-transpose payload (z >= 16).
// ---------------------------------------------------------------------------
__global__ void __launch_bounds__(256, 2)
logits_tr_kernel()
{
    if (blockIdx.z >= 16) {
        extern __shared__ char dsm_raw[];
        const int blin = (blockIdx.z - 16) * 16 + blockIdx.y * 4 + blockIdx.x; // 0..255
        const int tx = threadIdx.x & 31, ty = threadIdx.x >> 5;  // 32 x 8
        __half (*th)[34] = (__half(*)[34])(dsm_raw);
        __half (*tl)[34] = (__half(*)[34])(dsm_raw + 2304);
        for (int job = blin; job < 32768; job += 256) {
            const int nx = job & 255;                     // TWO_D/32
            const int sy = (job >> 8) & 15;               // SEQ/32
            const int b  = job >> 12;                     // NB
            const size_t sbase = (size_t)b * SEQ * TWO_D;
            const int s0 = sy * 32, n0 = nx * 32;
#pragma unroll
            for (int i = ty; i < 32; i += 8) {
                size_t o = sbase + (size_t)(s0 + i) * TWO_D + n0 + tx;
                th[i][tx] = g_vh[o];
                tl[i][tx] = g_vl[o];
            }
            __syncthreads();
            const size_t dbase = (size_t)b * TWO_D * SEQ;
#pragma unroll
            for (int i = ty; i < 32; i += 8) {
                size_t o = dbase + (size_t)(n0 + i) * SEQ + s0 + tx;
                g_vth[o] = th[tx][i];
                g_vtl[o] = tl[tx][i];
            }
            __syncthreads();
        }
        return;
    }
    const int bz = blockIdx.z;
    const int b = bz >> 1, pair = bz & 1;
    const int tm = blockIdx.y * 128, tn = blockIdx.x * 128;
    const size_t qoff = (size_t)b * SEQ * TWO_D + (size_t)pair * D_MODEL;
    float* C = (pair ? g_l2 : g_l1) + (size_t)b * SEQ * SEQ
             + (size_t)tm * SEQ + tn;
    gemm_body_3p128(g_qh + qoff + (size_t)tm * TWO_D,
                    g_ql + qoff + (size_t)tm * TWO_D, TWO_D,
                    g_kh + qoff + (size_t)tn * TWO_D,
                    g_kl + qoff + (size_t)tn * TWO_D, TWO_D,
                    D_MODEL, C, SEQ);
}

// Output GEMM: 128x128, 2 CTAs/SM.
__global__ void __launch_bounds__(256, 2)
out_gemm_kernel(float* __restrict__ out)
{
    const int b = blockIdx.z;
    int bx, by; remap_xy(4, bx, by);
    const int tm = by * 128, tn = bx * 128;
    const size_t soff = (size_t)b * SEQ * SEQ + (size_t)tm * SEQ;
    const size_t voff = (size_t)b * TWO_D * SEQ + (size_t)tn * SEQ;
    gemm_body_3p128(g_sch + soff, g_scl + soff, SEQ,
                    g_vth + voff, g_vtl + voff, SEQ,
                    SEQ, out + (size_t)b * SEQ * TWO_D + (size_t)tm * TWO_D + tn, TWO_D);
}

// ---------------------------------------------------------------------------
// Support kernels
// ---------------------------------------------------------------------------
__global__ void __launch_bounds__(256)
conv_xq_kernel(const float* __restrict__ x, const float* __restrict__ wq,
               int n4x, int n4w)
{
    const int idx = blockIdx.x * 256 + threadIdx.x;
    if (blockIdx.z == 0) {
        if (idx >= n4x) return;
        float4 v = ((const float4*)x)[idx];
        __half2* hp = (__half2*)(g_xh + (size_t)idx * 4);
        hp[0] = __halves2half2(__float2half_rn(v.x), __float2half_rn(v.y));
        hp[1] = __halves2half2(__float2half_rn(v.z), __float2half_rn(v.w));
        return;
    }
    if (idx >= n4w) return;
    float4 v = ((const float4*)wq)[idx];
    __half2 l0, l1;
    __half2 h0 = split_hl(v.x, v.y, l0);
    __half2 h1 = split_hl(v.z, v.w, l1);
    __half2* hp = (__half2*)(g_wqh + (size_t)idx * 4);
    hp[0] = h0; hp[1] = h1;
    __half2* lp = (__half2*)(g_wql + (size_t)idx * 4);
    lp[0] = l0; lp[1] = l1;
}

// Softmax over key axis + differential combine; writes f16 hi+lo scores
__global__ void __launch_bounds__(256)
softmax_combine_kernel(const float* __restrict__ lq1, const float* __restrict__ lk1,
                       const float* __restrict__ lq2, const float* __restrict__ lk2)
{
    const int r = blockIdx.x, b = blockIdx.y;
    const size_t off = ((size_t)b * SEQ + r) * SEQ;
    const float scale = 0.04419417382415922f;  // 1/sqrt(512)
    const int tid = threadIdx.x;
    const int lane = tid & 31, warp = tid >> 5;

    float v1a = g_l1[off + tid]       * scale;
    float v1b = g_l1[off + tid + 256] * scale;
    float v2a = g_l2[off + tid]       * scale;
    float v2b = g_l2[off + tid + 256] * scale;

    __shared__ float red1[8], red2[8];

    float m1 = fmaxf(v1a, v1b), m2 = fmaxf(v2a, v2b);
#pragma unroll
    for (int o = 16; o; o >>= 1) {
        m1 = fmaxf(m1, __shfl_xor_sync(0xffffffffu, m1, o));
        m2 = fmaxf(m2, __shfl_xor_sync(0xffffffffu, m2, o));
    }
    if (lane == 0) { red1[warp] = m1; red2[warp] = m2; }
    __syncthreads();
    m1 = red1[0]; m2 = red2[0];
#pragma unroll
    for (int i = 1; i < 8; i++) { m1 = fmaxf(m1, red1[i]); m2 = fmaxf(m2, red2[i]); }
    __syncthreads();

    float e1a = expf(v1a - m1), e1b = expf(v1b - m1);
    float e2a = expf(v2a - m2), e2b = expf(v2b - m2);
    float s1 = e1a + e1b, s2 = e2a + e2b;
#pragma unroll
    for (int o = 16; o; o >>= 1) {
        s1 += __shfl_xor_sync(0xffffffffu, s1, o);
        s2 += __shfl_xor_sync(0xffffffffu, s2, o);
    }
    if (lane == 0) { red1[warp] = s1; red2[warp] = s2; }
    __syncthreads();
    s1 = 0.f; s2 = 0.f;
#pragma unroll
    for (int i = 0; i < 8; i++) { s1 += red1[i]; s2 += red2[i]; }
    const float inv1 = 1.f / s1, inv2 = 1.f / s2;

#pragma unroll
    for (int half = 0; half < 2; half++) {
        const int k = tid + half * 256;
        float e1 = half ? e1b : e1a;
        float e2 = half ? e2b : e2a;
        float lam = expf(lq1[k] * lk1[k]) - expf(lq2[k] * lk2[k]) + LAMBDA_INIT;
        float v = e1 * inv1 - lam * (e2 * inv2);
        __half hh = __float2half_rn(v);
        g_sch[off + k] = hh;
        g_scl[off + k] = __float2half_rn(v - __half2float(hh));
    }
}

// ---------------------------------------------------------------------------
extern "C" void kernel_launch(void* const* d_in, const int* in_sizes, int n_in,
                              void* d_out, int out_size)
{
    const float* x    = (const float*)d_in[0];
    const float* wq_w = (const float*)d_in[1];
    const float* wq_b = (const float*)d_in[2];
    const float* wk_w = (const float*)d_in[3];
    const float* wk_b = (const float*)d_in[4];
    const float* wv_w = (const float*)d_in[5];
    const float* wv_b = (const float*)d_in[6];
    const float* lq1  = (const float*)d_in[7];
    const float* lk1  = (const float*)d_in[8];
    const float* lq2  = (const float*)d_in[9];
    const float* lk2  = (const float*)d_in[10];
    float* out = (float*)d_out;

    cudaFuncSetAttribute(proj_q_kernel,    cudaFuncAttributeMaxDynamicSharedMemorySize, DSMEM_BYTES_P);
    cudaFuncSetAttribute(proj_kv_kernel,   cudaFuncAttributeMaxDynamicSharedMemorySize, DSMEM_BYTES_P);
    cudaFuncSetAttribute(logits_tr_kernel, cudaFuncAttributeMaxDynamicSharedMemorySize, DSMEM_BYTES_L);
    cudaFuncSetAttribute(out_gemm_kernel,  cudaFuncAttributeMaxDynamicSharedMemorySize, DSMEM_BYTES_L);

    const int n4x = 4096 * 4096 / 4;
    const int n4w = TWO_D * 4096 / 4;

    // 0: convert x (hi) + wq (hi/lo)
    conv_xq_kernel<<<dim3(n4w / 256, 1, 2), 256>>>(x, wq_w, n4x, n4w);

    // 1: q projection + conv wk (z=1) + conv wv (z=2)
    dim3 projGridQ(TWO_D / 128, (NB * SEQ) / 128, 3);   // (64, 32, 3)
    proj_q_kernel<<<projGridQ, 256, DSMEM_BYTES_P>>>(wq_b, wk_w, wv_w);

    // 2: k + v projections merged (one tail instead of two)
    dim3 projGridKV(TWO_D / 128, (NB * SEQ) / 128, 2);  // (64, 32, 2)
    proj_kv_kernel<<<projGridKV, 256, DSMEM_BYTES_P>>>(wk_b, wv_b);

    // 3: logits + V transpose payload   <- profiled launch
    dim3 logitsGrid(SEQ / 128, SEQ / 128, 16 + 16);     // (4, 4, 32)
    logits_tr_kernel<<<logitsGrid, 256, DSMEM_BYTES_L>>>();

    // 4: softmax + differential combine
    dim3 smGrid(SEQ, NB);
    softmax_combine_kernel<<<smGrid, 256>>>(lq1, lk1, lq2, lk2);

    // 5: output GEMM
    dim3 outGrid(TWO_D / 128, SEQ / 128, NB);           // (64, 4, 8)
    out_gemm_kernel<<<outGrid, 256, DSMEM_BYTES_L>>>(out);
}

// round 17
// speedup vs baseline: 1.1268x; 1.0173x over previous
#include <cuda_runtime.h>
#include <cuda_fp16.h>
#include <cstdint>
#include <math.h>

// Problem constants
#define D_MODEL 4096
#define TWO_D   8192
#define NB      8
#define SEQ     512
#define LAMBDA_INIT 0.8f

// ---------------------------------------------------------------------------
// Scratch (static device globals; no runtime allocation allowed)
// ---------------------------------------------------------------------------
__device__ __align__(256) __half g_xh [(size_t)4096 * 4096];
__device__ __align__(256) __half g_wqh[(size_t)TWO_D * 4096];
__device__ __align__(256) __half g_wql[(size_t)TWO_D * 4096];
__device__ __align__(256) __half g_wkh[(size_t)TWO_D * 4096];
__device__ __align__(256) __half g_wkl[(size_t)TWO_D * 4096];
__device__ __align__(256) __half g_wvh[(size_t)TWO_D * 4096];
__device__ __align__(256) __half g_wvl[(size_t)TWO_D * 4096];
__device__ __align__(256) __half g_qh [(size_t)NB * SEQ * TWO_D];
__device__ __align__(256) __half g_ql [(size_t)NB * SEQ * TWO_D];
__device__ __align__(256) __half g_kh [(size_t)NB * SEQ * TWO_D];
__device__ __align__(256) __half g_kl [(size_t)NB * SEQ * TWO_D];
__device__ __align__(256) __half g_vth[(size_t)NB * TWO_D * SEQ];
__device__ __align__(256) __half g_vtl[(size_t)NB * TWO_D * SEQ];
__device__ __align__(256) float  g_l1 [(size_t)NB * SEQ * SEQ];
__device__ __align__(256) float  g_l2 [(size_t)NB * SEQ * SEQ];
__device__ __align__(256) __half g_sch[(size_t)NB * SEQ * SEQ];
__device__ __align__(256) __half g_scl[(size_t)NB * SEQ * SEQ];

// ---------------------------------------------------------------------------
// PTX primitives (arch-neutral: sm_80+)
// ---------------------------------------------------------------------------
__device__ __forceinline__ uint32_t smem_u32(const void* p) {
    uint32_t a;
    asm("{ .reg .u64 t; cvta.to.shared.u64 t, %1; cvt.u32.u64 %0, t; }"
        : "=r"(a) : "l"(p));
    return a;
}

__device__ __forceinline__ void cpa16(uint32_t dst, const void* src) {
    asm volatile("cp.async.cg.shared.global [%0], [%1], 16;\n"
                 :: "r"(dst), "l"(src));
}
#define CP_COMMIT() asm volatile("cp.async.commit_group;\n" ::: "memory")
#define CP_WAIT(N)  asm volatile("cp.async.wait_group %0;\n" :: "n"(N) : "memory")

#define LDSM4(R, addr) \
    asm volatile("ldmatrix.sync.aligned.m8n8.x4.shared.b16 {%0,%1,%2,%3}, [%4];" \
        : "=r"((R)[0]), "=r"((R)[1]), "=r"((R)[2]), "=r"((R)[3]) : "r"(addr))

__device__ __forceinline__ void mma_f16(float* c, const uint32_t* a,
                                        uint32_t b0, uint32_t b1) {
    asm volatile(
        "mma.sync.aligned.m16n8k16.row.col.f32.f16.f16.f32 "
        "{%0,%1,%2,%3}, {%4,%5,%6,%7}, {%8,%9}, {%0,%1,%2,%3};"
        : "+f"(c[0]), "+f"(c[1]), "+f"(c[2]), "+f"(c[3])
        : "r"(a[0]), "r"(a[1]), "r"(a[2]), "r"(a[3]), "r"(b0), "r"(b1));
}

// Swizzled smem byte offset: tile row r (64B rows), 16B-granule g
__device__ __forceinline__ uint32_t swz(uint32_t r, uint32_t g) {
    return r * 64u + (((g ^ ((r >> 1) & 3u)) << 4));
}

__device__ __forceinline__ __half2 split_hl(float a, float b, __half2& lo) {
    __half ha = __float2half_rn(a), hb = __float2half_rn(b);
    lo = __halves2half2(__float2half_rn(a - __half2float(ha)),
                        __float2half_rn(b - __half2float(hb)));
    return __halves2half2(ha, hb);
}

// ---------------------------------------------------------------------------
// Projection GEMM: C[128,128] = A[128,K] @ B[128,K]^T, fp16 2-product
// (AhBh + AhBl, A hi-only).  256 threads, 8 warps, warp tile 64x32,
// 4 stages x 24KB -> 2 CTAs/SM.
// TRANS=false: writes f16 hi/lo C[m][n] + bias.
// TRANS=true : writes f16 hi/lo C^T[n][m] + bias (smem-staged, coalesced) —
//              used by proj_v to produce vt directly (no transpose kernel).
// ---------------------------------------------------------------------------
#define BK       32
#define PSTAGE   24576
#define POFF_BH  8192
#define POFF_BL  16384
#define DSMEM_BYTES_P (4 * PSTAGE + 1024)        // 99,328 x2 = 198,656
#define TSTRIDE  136                             // halves; 16B-aligned rows

template<bool TRANS>
__device__ __forceinline__ void gemm_body_proj(
    const __half* __restrict__ Ah_, int lda,
    const __half* __restrict__ Bh_, const __half* __restrict__ Bl_, int ldb,
    int K, int ldc,
    __half* __restrict__ Ch, __half* __restrict__ Cl,
    const float* __restrict__ bias)
{
    extern __shared__ char dsm_raw[];
    const uint32_t sb = (smem_u32(dsm_raw) + 1023u) & ~1023u;

    const int tid  = threadIdx.x;
    const int wid  = tid >> 5;
    const int lane = tid & 31;
    const int warp_m = wid & 1;
    const int warp_n = wid >> 1;      // 4 in N (32 cols each)

    float acc[4][4][4];
#pragma unroll
    for (int i = 0; i < 4; i++)
#pragma unroll
        for (int j = 0; j < 4; j++)
#pragma unroll
            for (int q = 0; q < 4; q++) acc[i][j][q] = 0.f;

    const int rA = tid >> 2, gA = tid & 3;
    const uint32_t d0 = swz(rA, gA), d1 = swz(rA + 64, gA);
    const size_t aoff0 = (size_t)rA * lda + gA * 8;
    const size_t aoff1 = (size_t)(rA + 64) * lda + gA * 8;
    const size_t boff0 = (size_t)rA * ldb + gA * 8;
    const size_t boff1 = (size_t)(rA + 64) * ldb + gA * 8;

    auto load_stage = [&](int st, int kidx) {
        const int k0 = kidx * BK;
        const uint32_t sd = sb + st * PSTAGE;
        cpa16(sd + d0, Ah_ + aoff0 + k0);
        cpa16(sd + d1, Ah_ + aoff1 + k0);
        cpa16(sd + POFF_BH + d0, Bh_ + boff0 + k0);
        cpa16(sd + POFF_BH + d1, Bh_ + boff1 + k0);
        cpa16(sd + POFF_BL + d0, Bl_ + boff0 + k0);
        cpa16(sd + POFF_BL + d1, Bl_ + boff1 + k0);
    };

    const int kt = K / BK;
#pragma unroll
    for (int s = 0; s < 3; s++) {
        load_stage(s, s);
        CP_COMMIT();
    }

    const uint32_t a_row = warp_m * 64 + (lane & 7) + (((lane >> 3) & 1) << 3);
    const uint32_t a_gb  = lane >> 4;
    const uint32_t b_row = warp_n * 32 + (lane & 7) + ((lane >> 4) << 3);
    const uint32_t b_gb  = (lane >> 3) & 1;

    for (int it = 0; it < kt; it++) {
        CP_WAIT(2);
        __syncthreads();

        const int nf = it + 3;
        if (nf < kt) load_stage(nf & 3, nf);
        CP_COMMIT();

        const uint32_t st = sb + (it & 3) * PSTAGE;
#pragma unroll
        for (int ks = 0; ks < 2; ks++) {
            const uint32_t ag = ks * 2 + a_gb;
            const uint32_t bg = ks * 2 + b_gb;
            uint32_t ah[4][4];
#pragma unroll
            for (int mt = 0; mt < 4; mt++)
                LDSM4(ah[mt], st + swz(a_row + mt * 16, ag));
            uint32_t bh[2][4], bl[2][4];
#pragma unroll
            for (int nc = 0; nc < 2; nc++) {
                const uint32_t bd = st + swz(b_row + nc * 16, bg);
                LDSM4(bh[nc], bd + POFF_BH);
                LDSM4(bl[nc], bd + POFF_BL);
            }
#pragma unroll
            for (int mt = 0; mt < 4; mt++)
#pragma unroll
                for (int nt = 0; nt < 4; nt++) {
                    const int nc = nt >> 1, h = nt & 1;
                    mma_f16(acc[mt][nt], ah[mt], bh[nc][h * 2], bh[nc][h * 2 + 1]);
                }
#pragma unroll
            for (int mt = 0; mt < 4; mt++)
#pragma unroll
                for (int nt = 0; nt < 4; nt++) {
                    const int nc = nt >> 1, h = nt & 1;
                    mma_f16(acc[mt][nt], ah[mt], bl[nc][h * 2], bl[nc][h * 2 + 1]);
                }
        }
    }

    if (!TRANS) {
        // Direct f16 hi/lo epilogue
#pragma unroll
        for (int mt = 0; mt < 4; mt++) {
            const int r = warp_m * 64 + mt * 16 + (lane >> 2);
#pragma unroll
            for (int nt = 0; nt < 4; nt++) {
                const int c = warp_n * 32 + nt * 8 + (lane & 3) * 2;
                float2 bb = __ldg((const float2*)(bias + c));
                float v00 = acc[mt][nt][0] + bb.x, v01 = acc[mt][nt][1] + bb.y;
                float v10 = acc[mt][nt][2] + bb.x, v11 = acc[mt][nt][3] + bb.y;
                __half2 l0, l1;
                __half2 h0 = split_hl(v00, v01, l0);
                __half2 h1 = split_hl(v10, v11, l1);
                *(__half2*)(Ch + (size_t)r * ldc + c) = h0;
                *(__half2*)(Ch + (size_t)(r + 8) * ldc + c) = h1;
                *(__half2*)(Cl + (size_t)r * ldc + c) = l0;
                *(__half2*)(Cl + (size_t)(r + 8) * ldc + c) = l1;
            }
        }
    } else {
        // Transposed epilogue: scatter into smem as [n][m], then coalesced
        // row stores to Ch/Cl (vt layout: row = n, col = m, ldc = SEQ).
        __syncthreads();   // all warps done reading pipeline smem
        char* dp = (char*)(((uintptr_t)dsm_raw + 1023u) & ~(uintptr_t)1023u);
        __half* s_hi = (__half*)dp;
        __half* s_lo = s_hi + 128 * TSTRIDE;     // 2 x 34,816B <= 96KB
#pragma unroll
        for (int mt = 0; mt < 4; mt++) {
            const int r = warp_m * 64 + mt * 16 + (lane >> 2);
#pragma unroll
            for (int nt = 0; nt < 4; nt++) {
                const int c = warp_n * 32 + nt * 8 + (lane & 3) * 2;
                float2 bb = __ldg((const float2*)(bias + c));
                float v00 = acc[mt][nt][0] + bb.x, v01 = acc[mt][nt][1] + bb.y;
                float v10 = acc[mt][nt][2] + bb.x, v11 = acc[mt][nt][3] + bb.y;
                __half2 l0, l1;
                __half2 h0 = split_hl(v00, v01, l0);
                __half2 h1 = split_hl(v10, v11, l1);
                s_hi[(c    ) * TSTRIDE + r    ] = __low2half(h0);
                s_hi[(c + 1) * TSTRIDE + r    ] = __high2half(h0);
                s_hi[(c    ) * TSTRIDE + r + 8] = __low2half(h1);
                s_hi[(c + 1) * TSTRIDE + r + 8] = __high2half(h1);
                s_lo[(c    ) * TSTRIDE + r    ] = __low2half(l0);
                s_lo[(c + 1) * TSTRIDE + r    ] = __high2half(l0);
                s_lo[(c    ) * TSTRIDE + r + 8] = __low2half(l1);
                s_lo[(c + 1) * TSTRIDE + r + 8] = __high2half(l1);
            }
        }
        __syncthreads();
        // 256 threads: thread -> (n = tid&127, m-half = (tid>>7)*64)
        const int n  = tid & 127;
        const int mh = (tid >> 7) * 64;
        const uint4* srch = (const uint4*)(s_hi + n * TSTRIDE + mh);
        const uint4* srcl = (const uint4*)(s_lo + n * TSTRIDE + mh);
        uint4* dsth = (uint4*)(Ch + (size_t)n * ldc + mh);
        uint4* dstl = (uint4*)(Cl + (size_t)n * ldc + mh);
#pragma unroll
        for (int j = 0; j < 8; j++) dsth[j] = srch[j];
#pragma unroll
        for (int j = 0; j < 8; j++) dstl[j] = srcl[j];
    }
}

// ---------------------------------------------------------------------------
// 3-product GEMM (logits/output): C[128,128] = A[128,K] @ B[128,K]^T,
// (AhBh + AhBl + AlBh).  256 threads, warp tile 64x32,
// 3 stages x 32KB = 96KB -> 2 CTAs/SM.  fp32 epilogue.
// ---------------------------------------------------------------------------
#define LSTAGE   32768
#define LOFF_AL  8192
#define LOFF_BH  16384
#define LOFF_BL  24576
#define DSMEM_BYTES_L (3 * LSTAGE + 1024)        // 99,328 x2 = 198,656

__device__ __forceinline__ void gemm_body_3p128(
    const __half* __restrict__ Ah_, const __half* __restrict__ Al_, int lda,
    const __half* __restrict__ Bh_, const __half* __restrict__ Bl_, int ldb,
    int K, float* __restrict__ C, int ldc)
{
    extern __shared__ char dsm_raw[];
    const uint32_t sb = (smem_u32(dsm_raw) + 1023u) & ~1023u;

    const int tid  = threadIdx.x;
    const int wid  = tid >> 5;
    const int lane = tid & 31;
    const int warp_m = wid & 1;
    const int warp_n = wid >> 1;

    float acc[4][4][4];
#pragma unroll
    for (int i = 0; i < 4; i++)
#pragma unroll
        for (int j = 0; j < 4; j++)
#pragma unroll
            for (int q = 0; q < 4; q++) acc[i][j][q] = 0.f;

    const int rA = tid >> 2, gA = tid & 3;
    const uint32_t d0 = swz(rA, gA), d1 = swz(rA + 64, gA);
    const size_t aoff0 = (size_t)rA * lda + gA * 8;
    const size_t aoff1 = (size_t)(rA + 64) * lda + gA * 8;
    const size_t boff0 = (size_t)rA * ldb + gA * 8;
    const size_t boff1 = (size_t)(rA + 64) * ldb + gA * 8;

    auto load_stage = [&](int st, int kidx) {
        const int k0 = kidx * BK;
        const uint32_t sd = sb + st * LSTAGE;
        cpa16(sd + d0, Ah_ + aoff0 + k0);
        cpa16(sd + d1, Ah_ + aoff1 + k0);
        cpa16(sd + LOFF_AL + d0, Al_ + aoff0 + k0);
        cpa16(sd + LOFF_AL + d1, Al_ + aoff1 + k0);
        cpa16(sd + LOFF_BH + d0, Bh_ + boff0 + k0);
        cpa16(sd + LOFF_BH + d1, Bh_ + boff1 + k0);
        cpa16(sd + LOFF_BL + d0, Bl_ + boff0 + k0);
        cpa16(sd + LOFF_BL + d1, Bl_ + boff1 + k0);
    };

    const int kt = K / BK;
#pragma unroll
    for (int s = 0; s < 2; s++) {
        load_stage(s, s);
        CP_COMMIT();
    }

    const uint32_t a_row = warp_m * 64 + (lane & 7) + (((lane >> 3) & 1) << 3);
    const uint32_t a_gb  = lane >> 4;
    const uint32_t b_row = warp_n * 32 + (lane & 7) + ((lane >> 4) << 3);
    const uint32_t b_gb  = (lane >> 3) & 1;

    int slot = 0;
    for (int it = 0; it < kt; it++) {
        CP_WAIT(1);
        __syncthreads();

        const int nf = it + 2;
        if (nf < kt) {
            int ws = slot + 2; if (ws >= 3) ws -= 3;
            load_stage(ws, nf);
        }
        CP_COMMIT();

        const uint32_t st = sb + slot * LSTAGE;
        if (++slot == 3) slot = 0;
#pragma unroll
        for (int ks = 0; ks < 2; ks++) {
            const uint32_t ag = ks * 2 + a_gb;
            const uint32_t bg = ks * 2 + b_gb;
            uint32_t ah[4][4], al[4][4];
#pragma unroll
            for (int mt = 0; mt < 4; mt++) {
                const uint32_t ad = st + swz(a_row + mt * 16, ag);
                LDSM4(ah[mt], ad);
                LDSM4(al[mt], ad + LOFF_AL);
            }
            uint32_t bh[2][4], bl[2][4];
#pragma unroll
            for (int nc = 0; nc < 2; nc++) {
                const uint32_t bd = st + swz(b_row + nc * 16, bg);
                LDSM4(bh[nc], bd + LOFF_BH);
                LDSM4(bl[nc], bd + LOFF_BL);
            }
#pragma unroll
            for (int mt = 0; mt < 4; mt++)
#pragma unroll
                for (int nt = 0; nt < 4; nt++) {
                    const int nc = nt >> 1, h = nt & 1;
                    mma_f16(acc[mt][nt], ah[mt], bh[nc][h * 2], bh[nc][h * 2 + 1]);
                }
#pragma unroll
            for (int mt = 0; mt < 4; mt++)
#pragma unroll
                for (int nt = 0; nt < 4; nt++) {
                    const int nc = nt >> 1, h = nt & 1;
                    mma_f16(acc[mt][nt], ah[mt], bl[nc][h * 2], bl[nc][h * 2 + 1]);
                }
#pragma unroll
            for (int mt = 0; mt < 4; mt++)
#pragma unroll
                for (int nt = 0; nt < 4; nt++) {
                    const int nc = nt >> 1, h = nt & 1;
                    mma_f16(acc[mt][nt], al[mt], bh[nc][h * 2], bh[nc][h * 2 + 1]);
                }
        }
    }

#pragma unroll
    for (int mt = 0; mt < 4; mt++) {
        const int r = warp_m * 64 + mt * 16 + (lane >> 2);
#pragma unroll
        for (int nt = 0; nt < 4; nt++) {
            const int c = warp_n * 32 + nt * 8 + (lane & 3) * 2;
            float2 s;
            s.x = acc[mt][nt][0]; s.y = acc[mt][nt][1];
            *(float2*)(C + (size_t)r * ldc + c) = s;
            s.x = acc[mt][nt][2]; s.y = acc[mt][nt][3];
            *(float2*)(C + (size_t)(r + 8) * ldc + c) = s;
        }
    }
}

// Supertile remap for L2 reuse (G must divide gridDim.y)
__device__ __forceinline__ void remap_xy(int G, int& bx, int& by) {
    int lin = blockIdx.y * gridDim.x + blockIdx.x;
    int per = G * gridDim.x;
    int grp = lin / per, rem = lin % per;
    by = grp * G + (rem % G);
    bx = rem / G;
}

// ---------------------------------------------------------------------------
// Conversion payload (z-slab of proj_q launch): full weight hi/lo split
// ---------------------------------------------------------------------------
__device__ __forceinline__ void conv_w_block(const float* __restrict__ src,
                                             __half* __restrict__ h,
                                             __half* __restrict__ l)
{
    const int nblk = gridDim.x * gridDim.y;
    const int per = (TWO_D * 4096 / 4) / nblk;
    const int blin = blockIdx.y * gridDim.x + blockIdx.x;
    const size_t base = (size_t)blin * per;
    const float4* s4 = (const float4*)src;
    for (int i = threadIdx.x; i < per; i += blockDim.x) {
        const size_t idx = base + i;
        float4 v = s4[idx];
        __half2 l0, l1;
        __half2 h0 = split_hl(v.x, v.y, l0);
        __half2 h1 = split_hl(v.z, v.w, l1);
        __half2* hp = (__half2*)(h + idx * 4);
        hp[0] = h0; hp[1] = h1;
        __half2* lp = (__half2*)(l + idx * 4);
        lp[0] = l0; lp[1] = l1;
    }
}

// ---------------------------------------------------------------------------
// proj_q: GEMM (z=0) + conv wk (z=1) + conv wv (z=2).
// ---------------------------------------------------------------------------
__global__ void __launch_bounds__(256, 2)
proj_q_kernel(const float* __restrict__ bias,
              const float* __restrict__ wk_src, const float* __restrict__ wv_src)
{
    if (blockIdx.z == 1) { conv_w_block(wk_src, g_wkh, g_wkl); return; }
    if (blockIdx.z == 2) { conv_w_block(wv_src, g_wvh, g_wvl); return; }
    int bx, by; remap_xy(8, bx, by);
    const int tm = by * 128, tn = bx * 128;
    gemm_body_proj<false>(g_xh + (size_t)tm * D_MODEL, D_MODEL,
                          g_wqh + (size_t)tn * D_MODEL, g_wql + (size_t)tn * D_MODEL, D_MODEL,
                          D_MODEL, TWO_D,
                          g_qh + (size_t)tm * TWO_D + tn, g_ql + (size_t)tm * TWO_D + tn,
                          bias + tn);
}

// ---------------------------------------------------------------------------
// proj_kv: K projection (z=0) and V projection (z=1, TRANSPOSED output).
// V writes straight into vt layout — no separate transpose pass.
// ---------------------------------------------------------------------------
__global__ void __launch_bounds__(256, 2)
proj_kv_kernel(const float* __restrict__ bias_k, const float* __restrict__ bias_v)
{
    int bx, by; remap_xy(8, bx, by);
    const int tm = by * 128, tn = bx * 128;
    if (blockIdx.z == 0) {
        gemm_body_proj<false>(g_xh + (size_t)tm * D_MODEL, D_MODEL,
                              g_wkh + (size_t)tn * D_MODEL, g_wkl + (size_t)tn * D_MODEL, D_MODEL,
                              D_MODEL, TWO_D,
                              g_kh + (size_t)tm * TWO_D + tn, g_kl + (size_t)tm * TWO_D + tn,
                              bias_k + tn);
    } else {
        // vt[b][n][s]: tile rows = n (tn..tn+127), cols = s (within batch b)
        const int b = tm >> 9;           // 512 rows per batch
        const int s0 = tm & 511;
        __half* CtH = g_vth + (size_t)b * TWO_D * SEQ + (size_t)tn * SEQ + s0;
        __half* CtL = g_vtl + (size_t)b * TWO_D * SEQ + (size_t)tn * SEQ + s0;
        gemm_body_proj<true>(g_xh + (size_t)tm * D_MODEL, D_MODEL,
                             g_wvh + (size_t)tn * D_MODEL, g_wvl + (size_t)tn * D_MODEL, D_MODEL,
                             D_MODEL, SEQ, CtH, CtL, bias_v + tn);
    }
}

// ---------------------------------------------------------------------------
// Logits GEMM (pure): 128x128, 2 CTAs/SM, grid (4, 4, 16).
// ---------------------------------------------------------------------------
__global__ void __launch_bounds__(256, 2)
logits_kernel()
{
    const int bz = blockIdx.z;
    const int b = bz >> 1, pair = bz & 1;
    const int tm = blockIdx.y * 128, tn = blockIdx.x * 128;
    const size_t qoff = (size_t)b * SEQ * TWO_D + (size_t)pair * D_MODEL;
    float* C = (pair ? g_l2 : g_l1) + (size_t)b * SEQ * SEQ
             + (size_t)tm * SEQ + tn;
    gemm_body_3p128(g_qh + qoff + (size_t)tm * TWO_D,
                    g_ql + qoff + (size_t)tm * TWO_D, TWO_D,
                    g_kh + qoff + (size_t)tn * TWO_D,
                    g_kl + qoff + (size_t)tn * TWO_D, TWO_D,
                    D_MODEL, C, SEQ);
}

// Output GEMM: 128x128, 2 CTAs/SM.
__global__ void __launch_bounds__(256, 2)
out_gemm_kernel(float* __restrict__ out)
{
    const int b = blockIdx.z;
    int bx, by; remap_xy(4, bx, by);
    const int tm = by * 128, tn = bx * 128;
    const size_t soff = (size_t)b * SEQ * SEQ + (size_t)tm * SEQ;
    const size_t voff = (size_t)b * TWO_D * SEQ + (size_t)tn * SEQ;
    gemm_body_3p128(g_sch + soff, g_scl + soff, SEQ,
                    g_vth + voff, g_vtl + voff, SEQ,
                    SEQ, out + (size_t)b * SEQ * TWO_D + (size_t)tm * TWO_D + tn, TWO_D);
}

// ---------------------------------------------------------------------------
// Support kernels
// ---------------------------------------------------------------------------
__global__ void __launch_bounds__(256)
conv_xq_kernel(const float* __restrict__ x, const float* __restrict__ wq,
               int n4x, int n4w)
{
    const int idx = blockIdx.x * 256 + threadIdx.x;
    if (blockIdx.z == 0) {
        if (idx >= n4x) return;
        float4 v = ((const float4*)x)[idx];
        __half2* hp = (__half2*)(g_xh + (size_t)idx * 4);
        hp[0] = __halves2half2(__float2half_rn(v.x), __float2half_rn(v.y));
        hp[1] = __halves2half2(__float2half_rn(v.z), __float2half_rn(v.w));
        return;
    }
    if (idx >= n4w) return;
    float4 v = ((const float4*)wq)[idx];
    __half2 l0, l1;
    __half2 h0 = split_hl(v.x, v.y, l0);
    __half2 h1 = split_hl(v.z, v.w, l1);
    __half2* hp = (__half2*)(g_wqh + (size_t)idx * 4);
    hp[0] = h0; hp[1] = h1;
    __half2* lp = (__half2*)(g_wql + (size_t)idx * 4);
    lp[0] = l0; lp[1] = l1;
}

// Softmax over key axis + differential combine; writes f16 hi+lo scores
__global__ void __launch_bounds__(256)
softmax_combine_kernel(const float* __restrict__ lq1, const float* __restrict__ lk1,
                       const float* __restrict__ lq2, const float* __restrict__ lk2)
{
    const int r = blockIdx.x, b = blockIdx.y;
    const size_t off = ((size_t)b * SEQ + r) * SEQ;
    const float scale = 0.04419417382415922f;  // 1/sqrt(512)
    const int tid = threadIdx.x;
    const int lane = tid & 31, warp = tid >> 5;

    float v1a = g_l1[off + tid]       * scale;
    float v1b = g_l1[off + tid + 256] * scale;
    float v2a = g_l2[off + tid]       * scale;
    float v2b = g_l2[off + tid + 256] * scale;

    __shared__ float red1[8], red2[8];

    float m1 = fmaxf(v1a, v1b), m2 = fmaxf(v2a, v2b);
#pragma unroll
    for (int o = 16; o; o >>= 1) {
        m1 = fmaxf(m1, __shfl_xor_sync(0xffffffffu, m1, o));
        m2 = fmaxf(m2, __shfl_xor_sync(0xffffffffu, m2, o));
    }
    if (lane == 0) { red1[warp] = m1; red2[warp] = m2; }
    __syncthreads();
    m1 = red1[0]; m2 = red2[0];
#pragma unroll
    for (int i = 1; i < 8; i++) { m1 = fmaxf(m1, red1[i]); m2 = fmaxf(m2, red2[i]); }
    __syncthreads();

    float e1a = expf(v1a - m1), e1b = expf(v1b - m1);
    float e2a = expf(v2a - m2), e2b = expf(v2b - m2);
    float s1 = e1a + e1b, s2 = e2a + e2b;
#pragma unroll
    for (int o = 16; o; o >>= 1) {
        s1 += __shfl_xor_sync(0xffffffffu, s1, o);
        s2 += __shfl_xor_sync(0xffffffffu, s2, o);
    }
    if (lane == 0) { red1[warp] = s1; red2[warp] = s2; }
    __syncthreads();
    s1 = 0.f; s2 = 0.f;
#pragma unroll
    for (int i = 0; i < 8; i++) { s1 += red1[i]; s2 += red2[i]; }
    const float inv1 = 1.f / s1, inv2 = 1.f / s2;

#pragma unroll
    for (int half = 0; half < 2; half++) {
        const int k = tid + half * 256;
        float e1 = half ? e1b : e1a;
        float e2 = half ? e2b : e2a;
        float lam = expf(lq1[k] * lk1[k]) - expf(lq2[k] * lk2[k]) + LAMBDA_INIT;
        float v = e1 * inv1 - lam * (e2 * inv2);
        __half hh = __float2half_rn(v);
        g_sch[off + k] = hh;
        g_scl[off + k] = __float2half_rn(v - __half2float(hh));
    }
}

// ---------------------------------------------------------------------------
extern "C" void kernel_launch(void* const* d_in, const int* in_sizes, int n_in,
                              void* d_out, int out_size)
{
    const float* x    = (const float*)d_in[0];
    const float* wq_w = (const float*)d_in[1];
    const float* wq_b = (const float*)d_in[2];
    const float* wk_w = (const float*)d_in[3];
    const float* wk_b = (const float*)d_in[4];
    const float* wv_w = (const float*)d_in[5];
    const float* wv_b = (const float*)d_in[6];
    const float* lq1  = (const float*)d_in[7];
    const float* lk1  = (const float*)d_in[8];
    const float* lq2  = (const float*)d_in[9];
    const float* lk2  = (const float*)d_in[10];
    float* out = (float*)d_out;

    cudaFuncSetAttribute(proj_q_kernel,   cudaFuncAttributeMaxDynamicSharedMemorySize, DSMEM_BYTES_P);
    cudaFuncSetAttribute(proj_kv_kernel,  cudaFuncAttributeMaxDynamicSharedMemorySize, DSMEM_BYTES_P);
    cudaFuncSetAttribute(logits_kernel,   cudaFuncAttributeMaxDynamicSharedMemorySize, DSMEM_BYTES_L);
    cudaFuncSetAttribute(out_gemm_kernel, cudaFuncAttributeMaxDynamicSharedMemorySize, DSMEM_BYTES_L);

    const int n4x = 4096 * 4096 / 4;
    const int n4w = TWO_D * 4096 / 4;

    // 0: convert x (hi) + wq (hi/lo)
    conv_xq_kernel<<<dim3(n4w / 256, 1, 2), 256>>>(x, wq_w, n4x, n4w);

    // 1: q projection + conv wk (z=1) + conv wv (z=2)
    dim3 projGridQ(TWO_D / 128, (NB * SEQ) / 128, 3);   // (64, 32, 3)
    proj_q_kernel<<<projGridQ, 256, DSMEM_BYTES_P>>>(wq_b, wk_w, wv_w);

    // 2: k + v projections merged; v writes vt directly (fused transpose)
    dim3 projGridKV(TWO_D / 128, (NB * SEQ) / 128, 2);  // (64, 32, 2)
    proj_kv_kernel<<<projGridKV, 256, DSMEM_BYTES_P>>>(wk_b, wv_b);

    // 3: logits (pure)   <- profiled launch
    dim3 logitsGrid(SEQ / 128, SEQ / 128, 16);          // (4, 4, 16)
    logits_kernel<<<logitsGrid, 256, DSMEM_BYTES_L>>>();

    // 4: softmax + differential combine
    dim3 smGrid(SEQ, NB);
    softmax_combine_kernel<<<smGrid, 256>>>(lq1, lk1, lq2, lk2);

    // 5: output GEMM
    dim3 outGrid(TWO_D / 128, SEQ / 128, NB);           // (64, 4, 8)
    out_gemm_kernel<<<outGrid, 256, DSMEM_BYTES_L>>>(out);
}